// round 2
// baseline (speedup 1.0000x reference)
#include <cuda_runtime.h>
#include <math.h>

#define B_ 32
#define C_ 256
#define L_ 4096
#define H_ (2*C_)
#define BL_ (B_*L_)
#define KC_ (3*C_)   // 768, conv GEMM depth

typedef unsigned long long u64;

// packed dual-fp32 FMA: d = a*b + d (elementwise on two packed floats)
__device__ __forceinline__ void ffma2(u64& d, u64 a, u64 b) {
    asm("fma.rn.f32x2 %0, %1, %2, %3;" : "=l"(d) : "l"(a), "l"(b), "l"(d));
}

// ---------------- scratch (device globals; no allocation allowed) ----------
__device__ float g_y1[(size_t)B_*C_*L_];   // conv1 output [B,C,L]
__device__ float g_xp[(size_t)B_*L_*C_];   // conv2 output transposed [B,L,C]
__device__ float g_t1[(size_t)B_*L_*C_];   // freq / sd / fw  [B*L, C]
__device__ float g_h [(size_t)B_*L_*H_];   // hidden [B*L, 2C]
__device__ float g_dct [C_*C_];            // [n][k] = Dm[k][n]
__device__ float g_fc1t[C_*H_];            // [c][j] = fc1_w[j][c]
__device__ float g_fc2t[H_*C_];            // [j][c] = fc2_w[c][j]

// ---------------- precompute: DCT matrix + transposed fc weights -----------
__global__ void precompute_kernel(const float* __restrict__ fc1_w,
                                  const float* __restrict__ fc2_w) {
    int idx = blockIdx.x * blockDim.x + threadIdx.x;
    if (idx < C_*C_) {
        int n = idx / C_, k = idx % C_;
        double v = 2.0 * cos(M_PI * (double)k * (2.0*n + 1.0) / (2.0 * C_));
        g_dct[n*C_ + k] = (float)v;
    }
    if (idx < C_*H_) {
        int c = idx / H_, j = idx % H_;
        g_fc1t[c*H_ + j] = fc1_w[j*C_ + c];   // fc1_w: [2C, C]
        g_fc2t[j*C_ + c] = fc2_w[c*H_ + j];   // fc2_w: [C, 2C]
    }
}

#define GM 128
#define GN 128
#define GK 8

// ============ conv1d(K=3,pad=1) as GEMM: Y[co,l] = W[co,(ci,k)] X[(ci,k),l] =
// A = conv weight [C, 3C] (native layout). B row (ci,k) = x[ci, l+k-1].
// Fused eval-BN (+relu); optional transposed [B,L,C] output.
__global__ void conv_gemm_kernel(const float* __restrict__ X,
                                 const float* __restrict__ W,
                                 const float* __restrict__ bng, const float* __restrict__ bnb,
                                 const float* __restrict__ bnm, const float* __restrict__ bnv,
                                 float* __restrict__ Y, int do_relu, int transpose_out) {
    __shared__ __align__(16) float As2[GK][2*GM];  // duplicated pairs (a,a)
    __shared__ __align__(16) float Bs[GK][GN];
    int b  = blockIdx.z;
    int m0 = blockIdx.y * GM;   // co
    int l0 = blockIdx.x * GN;   // l
    int tid = threadIdx.x;      // 256
    int tx = tid & 15, ty = tid >> 4;
    const float* xb = X + (size_t)b * C_ * L_;

    u64 acc2[8][4] = {};
    int a_row = tid >> 1;
    int a_col = (tid & 1) * 4;
    int b_row = tid >> 5;            // 8 K-rows
    int b_col = (tid & 31) * 4;      // 128 l columns

    for (int k0 = 0; k0 < KC_; k0 += GK) {
        float4 av = *(const float4*)&W[(size_t)(m0 + a_row)*KC_ + k0 + a_col];
        As2[a_col+0][2*a_row] = av.x; As2[a_col+0][2*a_row+1] = av.x;
        As2[a_col+1][2*a_row] = av.y; As2[a_col+1][2*a_row+1] = av.y;
        As2[a_col+2][2*a_row] = av.z; As2[a_col+2][2*a_row+1] = av.z;
        As2[a_col+3][2*a_row] = av.w; As2[a_col+3][2*a_row+1] = av.w;

        int kr = k0 + b_row;
        int ci = kr / 3;
        int ko = kr - 3*ci;                       // 0..2
        const float* xrow = xb + (size_t)ci * L_;
        int gbase = l0 + b_col + ko - 1;
        #pragma unroll
        for (int jj = 0; jj < 4; jj++) {
            int gl = gbase + jj;
            Bs[b_row][b_col + jj] = ((unsigned)gl < (unsigned)L_) ? __ldg(&xrow[gl]) : 0.f;
        }
        __syncthreads();
        #pragma unroll
        for (int kk = 0; kk < GK; kk++) {
            u64 ar2[8], br2[4];
            const u64* ap = (const u64*)&As2[kk][ty*16];
            const u64* bp = (const u64*)&Bs[kk][tx*8];
            #pragma unroll
            for (int q = 0; q < 8; q++) ar2[q] = ap[q];
            #pragma unroll
            for (int q = 0; q < 4; q++) br2[q] = bp[q];
            #pragma unroll
            for (int i = 0; i < 8; i++)
                #pragma unroll
                for (int j = 0; j < 4; j++)
                    ffma2(acc2[i][j], ar2[i], br2[j]);
        }
        __syncthreads();
    }

    // unpack + BN (+relu)
    float vals[8][8];
    #pragma unroll
    for (int i = 0; i < 8; i++) {
        int co = m0 + ty*8 + i;
        float scale = bng[co] * rsqrtf(bnv[co] + 1e-5f);
        float shift = bnb[co] - bnm[co]*scale;
        #pragma unroll
        for (int j = 0; j < 4; j++) {
            float2 p = *(float2*)&acc2[i][j];
            float u0 = p.x*scale + shift, u1 = p.y*scale + shift;
            if (do_relu) { u0 = fmaxf(u0, 0.f); u1 = fmaxf(u1, 0.f); }
            vals[i][2*j] = u0; vals[i][2*j+1] = u1;
        }
    }
    if (!transpose_out) {
        #pragma unroll
        for (int i = 0; i < 8; i++) {
            size_t base = ((size_t)b*C_ + m0 + ty*8 + i)*L_ + l0 + tx*8;
            *(float4*)&Y[base]   = make_float4(vals[i][0], vals[i][1], vals[i][2], vals[i][3]);
            *(float4*)&Y[base+4] = make_float4(vals[i][4], vals[i][5], vals[i][6], vals[i][7]);
        }
    } else {
        #pragma unroll
        for (int j = 0; j < 8; j++) {
            int l = l0 + tx*8 + j;
            size_t base = ((size_t)b*L_ + l)*C_ + m0 + ty*8;
            *(float4*)&Y[base]   = make_float4(vals[0][j], vals[1][j], vals[2][j], vals[3][j]);
            *(float4*)&Y[base+4] = make_float4(vals[4][j], vals[5][j], vals[6][j], vals[7][j]);
        }
    }
}

// ---------------- SGEMM 128x128x8, FFMA2 inner loop, fused epilogue --------
// C[M,N] = A[M,K] @ B[K,N]; M%128==0, N%128==0, K%8==0
__global__ void sgemm_kernel(const float* __restrict__ A, const float* __restrict__ B,
                             float* __restrict__ C, int M, int N, int K, int epi) {
    __shared__ __align__(16) float As2[GK][2*GM];
    __shared__ __align__(16) float Bs[GK][GN];
    int tid = threadIdx.x;            // 256
    size_t m0 = (size_t)blockIdx.y * GM;
    size_t n0 = (size_t)blockIdx.x * GN;
    int tx = tid & 15, ty = tid >> 4;

    u64 acc2[8][4] = {};
    int a_row = tid >> 1;
    int a_col = (tid & 1) * 4;
    int b_row = tid >> 5;
    int b_col = (tid & 31) * 4;

    for (int k0 = 0; k0 < K; k0 += GK) {
        float4 av = *(const float4*)&A[(m0 + a_row)*K + k0 + a_col];
        As2[a_col+0][2*a_row] = av.x; As2[a_col+0][2*a_row+1] = av.x;
        As2[a_col+1][2*a_row] = av.y; As2[a_col+1][2*a_row+1] = av.y;
        As2[a_col+2][2*a_row] = av.z; As2[a_col+2][2*a_row+1] = av.z;
        As2[a_col+3][2*a_row] = av.w; As2[a_col+3][2*a_row+1] = av.w;
        *(float4*)&Bs[b_row][b_col] = *(const float4*)&B[(size_t)(k0 + b_row)*N + n0 + b_col];
        __syncthreads();
        #pragma unroll
        for (int kk = 0; kk < GK; kk++) {
            u64 ar2[8], br2[4];
            const u64* ap = (const u64*)&As2[kk][ty*16];
            const u64* bp = (const u64*)&Bs[kk][tx*8];
            #pragma unroll
            for (int q = 0; q < 8; q++) ar2[q] = ap[q];
            #pragma unroll
            for (int q = 0; q < 4; q++) br2[q] = bp[q];
            #pragma unroll
            for (int i = 0; i < 8; i++)
                #pragma unroll
                for (int j = 0; j < 4; j++)
                    ffma2(acc2[i][j], ar2[i], br2[j]);
        }
        __syncthreads();
    }
    #pragma unroll
    for (int i = 0; i < 8; i++) {
        size_t row = m0 + ty*8 + i;
        float v[8];
        #pragma unroll
        for (int j = 0; j < 4; j++) {
            float2 p = *(float2*)&acc2[i][j];
            v[2*j] = p.x; v[2*j+1] = p.y;
        }
        #pragma unroll
        for (int j = 0; j < 8; j++) {
            float u = v[j];
            if (epi == 1) u = fmaxf(u, 0.f);
            else if (epi == 2) u = 1.f/(1.f + expf(-u));
            v[j] = u;
        }
        *(float4*)&C[row*N + n0 + tx*8]     = make_float4(v[0], v[1], v[2], v[3]);
        *(float4*)&C[row*N + n0 + tx*8 + 4] = make_float4(v[4], v[5], v[6], v[7]);
    }
}

// ---------------- LayerNorm over last dim (C_=256), in-place ---------------
__global__ void ln_kernel(float* __restrict__ data,
                          const float* __restrict__ g, const float* __restrict__ b) {
    __shared__ float sh[8];
    size_t row = blockIdx.x;
    float* p = data + row * C_;
    int t = threadIdx.x;      // 256
    int lane = t & 31, wid = t >> 5;
    float v = p[t];

    float s = v;
    #pragma unroll
    for (int o = 16; o; o >>= 1) s += __shfl_xor_sync(0xffffffffu, s, o);
    if (lane == 0) sh[wid] = s;
    __syncthreads();
    if (wid == 0) {
        float r = (lane < 8) ? sh[lane] : 0.f;
        #pragma unroll
        for (int o = 4; o; o >>= 1) r += __shfl_xor_sync(0xffffffffu, r, o);
        if (lane == 0) sh[0] = r;
    }
    __syncthreads();
    float mean = sh[0] * (1.f / C_);
    __syncthreads();

    float d = v - mean;
    float s2 = d * d;
    #pragma unroll
    for (int o = 16; o; o >>= 1) s2 += __shfl_xor_sync(0xffffffffu, s2, o);
    if (lane == 0) sh[wid] = s2;
    __syncthreads();
    if (wid == 0) {
        float r = (lane < 8) ? sh[lane] : 0.f;
        #pragma unroll
        for (int o = 4; o; o >>= 1) r += __shfl_xor_sync(0xffffffffu, r, o);
        if (lane == 0) sh[0] = r;
    }
    __syncthreads();
    float var = sh[0] * (1.f / C_);
    p[t] = d * rsqrtf(var + 1e-6f) * g[t] + b[t];
}

// ------- final: out[b,c,l] = relu(xp[b,l,c]*fw[b,l,c] + x[b,c,l]) ----------
__global__ void final_kernel(const float* __restrict__ xp, const float* __restrict__ fw,
                             const float* __restrict__ x, float* __restrict__ out) {
    __shared__ float tile[32][33];
    int b  = blockIdx.z;
    int c0 = blockIdx.x * 32;
    int l0 = blockIdx.y * 32;
    int tx = threadIdx.x, ty = threadIdx.y;   // 32 x 8
    #pragma unroll
    for (int i = 0; i < 32; i += 8) {
        int l = l0 + ty + i;
        size_t idx = ((size_t)b*L_ + l)*C_ + c0 + tx;
        tile[ty+i][tx] = xp[idx] * fw[idx];
    }
    __syncthreads();
    #pragma unroll
    for (int i = 0; i < 32; i += 8) {
        int c = c0 + ty + i;
        int l = l0 + tx;
        size_t idx = ((size_t)b*C_ + c)*L_ + l;
        out[idx] = fmaxf(tile[tx][ty+i] + x[idx], 0.f);
    }
}

// ---------------------------------------------------------------------------
extern "C" void kernel_launch(void* const* d_in, const int* in_sizes, int n_in,
                              void* d_out, int out_size) {
    const float* x       = (const float*)d_in[0];
    const float* conv1_w = (const float*)d_in[1];
    const float* bn1_g   = (const float*)d_in[2];
    const float* bn1_b   = (const float*)d_in[3];
    const float* bn1_m   = (const float*)d_in[4];
    const float* bn1_v   = (const float*)d_in[5];
    const float* conv2_w = (const float*)d_in[6];
    const float* bn2_g   = (const float*)d_in[7];
    const float* bn2_b   = (const float*)d_in[8];
    const float* bn2_m   = (const float*)d_in[9];
    const float* bn2_v   = (const float*)d_in[10];
    const float* fc1_w   = (const float*)d_in[11];
    const float* fc2_w   = (const float*)d_in[12];
    const float* ln_g    = (const float*)d_in[13];
    const float* ln_b    = (const float*)d_in[14];
    float* out = (float*)d_out;

    float *y1, *xp, *t1, *h, *dct, *fc1t, *fc2t;
    cudaGetSymbolAddress((void**)&y1,   g_y1);
    cudaGetSymbolAddress((void**)&xp,   g_xp);
    cudaGetSymbolAddress((void**)&t1,   g_t1);
    cudaGetSymbolAddress((void**)&h,    g_h);
    cudaGetSymbolAddress((void**)&dct,  g_dct);
    cudaGetSymbolAddress((void**)&fc1t, g_fc1t);
    cudaGetSymbolAddress((void**)&fc2t, g_fc2t);

    // 0. precompute DCT matrix + transposed weights
    precompute_kernel<<<(C_*H_ + 255)/256, 256>>>(fc1_w, fc2_w);

    // 1. conv1 + bn1 + relu -> y1 [B,C,L]   (conv as M=256,N=4096,K=768 GEMM)
    {
        dim3 grid(L_/GN, C_/GM, B_);
        conv_gemm_kernel<<<grid, 256>>>(x, conv1_w, bn1_g, bn1_b, bn1_m, bn1_v,
                                        y1, /*relu=*/1, /*transpose=*/0);
    }
    // 2. conv2 + bn2 -> xp [B,L,C] (transposed)
    {
        dim3 grid(L_/GN, C_/GM, B_);
        conv_gemm_kernel<<<grid, 256>>>(y1, conv2_w, bn2_g, bn2_b, bn2_m, bn2_v,
                                        xp, /*relu=*/0, /*transpose=*/1);
    }
    // 3. freq = xp @ Dm^T  -> t1 [BL, C]
    {
        dim3 grid(C_/GN, BL_/GM);
        sgemm_kernel<<<grid, 256>>>(xp, dct, t1, BL_, C_, C_, /*epi=*/0);
    }
    // 4. sd = LN(freq), in place
    ln_kernel<<<BL_, C_>>>(t1, ln_g, ln_b);

    // 5. h = relu(sd @ fc1^T) -> g_h [BL, 2C]
    {
        dim3 grid(H_/GN, BL_/GM);
        sgemm_kernel<<<grid, 256>>>(t1, fc1t, h, BL_, H_, C_, /*epi=*/1);
    }
    // 6. fw = sigmoid(h @ fc2^T) -> t1 [BL, C]
    {
        dim3 grid(C_/GN, BL_/GM);
        sgemm_kernel<<<grid, 256>>>(h, fc2t, t1, BL_, C_, H_, /*epi=*/2);
    }
    // 7. fw = LN(fw), in place
    ln_kernel<<<BL_, C_>>>(t1, ln_g, ln_b);

    // 8. out = relu(transpose(xp * fw) + x)
    {
        dim3 grid(C_/32, L_/32, B_);
        final_kernel<<<grid, dim3(32, 8)>>>(xp, t1, x, out);
    }
}

// round 3
// speedup vs baseline: 1.2171x; 1.2171x over previous
#include <cuda_runtime.h>
#include <math.h>

#define B_ 32
#define C_ 256
#define L_ 4096
#define H_ (2*C_)
#define BL_ (B_*L_)
#define KC_ (3*C_)   // 768, conv GEMM depth

// ---------------- scratch (device globals; no allocation allowed) ----------
__device__ float g_y1[(size_t)B_*C_*L_];   // conv1 output [B,C,L]
__device__ float g_xp[(size_t)B_*L_*C_];   // conv2 output transposed [B,L,C]
__device__ float g_t1[(size_t)B_*L_*C_];   // freq / sd / fw  [B*L, C]
__device__ float g_h [(size_t)B_*L_*H_];   // hidden [B*L, 2C]
__device__ float g_dct [C_*C_];            // [n][k] = Dm[k][n]
__device__ float g_fc1t[C_*H_];            // [c][j] = fc1_w[j][c]
__device__ float g_fc2t[H_*C_];            // [j][c] = fc2_w[c][j]

// ---------------- precompute: DCT matrix + transposed fc weights -----------
__global__ void precompute_kernel(const float* __restrict__ fc1_w,
                                  const float* __restrict__ fc2_w) {
    int idx = blockIdx.x * blockDim.x + threadIdx.x;
    if (idx < C_*C_) {
        int n = idx / C_, k = idx % C_;
        double v = 2.0 * cos(M_PI * (double)k * (2.0*n + 1.0) / (2.0 * C_));
        g_dct[n*C_ + k] = (float)v;
    }
    if (idx < C_*H_) {
        int c = idx / H_, j = idx % H_;
        g_fc1t[c*H_ + j] = fc1_w[j*C_ + c];   // fc1_w: [2C, C]
        g_fc2t[j*C_ + c] = fc2_w[c*H_ + j];   // fc2_w: [C, 2C]
    }
}

#define GM 128
#define GN 128
#define GK 8

// ============ conv1d(K=3,pad=1) as GEMM: Y[co,l] = W[co,(ci,k)] X[(ci,k),l]
// A = conv weight [C, 3C] (native layout). B row (ci,k) = x[ci, l+k-1].
// Plain-FFMA 128x128x8 macrokernel (round-1 proven inner loop).
// Fused eval-BN (+relu); optional transposed [B,L,C] output.
__global__ void conv_gemm_kernel(const float* __restrict__ X,
                                 const float* __restrict__ W,
                                 const float* __restrict__ bng, const float* __restrict__ bnb,
                                 const float* __restrict__ bnm, const float* __restrict__ bnv,
                                 float* __restrict__ Y, int do_relu, int transpose_out) {
    __shared__ __align__(16) float As[GK][GM];
    __shared__ __align__(16) float Bs[GK][GN];
    int b  = blockIdx.z;
    int m0 = blockIdx.y * GM;   // co
    int l0 = blockIdx.x * GN;   // l
    int tid = threadIdx.x;      // 256
    int tx = tid & 15, ty = tid >> 4;
    const float* xb = X + (size_t)b * C_ * L_;

    float acc[8][8] = {};
    int a_row = tid >> 1;
    int a_col = (tid & 1) * 4;
    int b_row = tid >> 5;            // 8 K-rows
    int b_col = (tid & 31) * 4;      // 128 l columns

    for (int k0 = 0; k0 < KC_; k0 += GK) {
        float4 av = *(const float4*)&W[(size_t)(m0 + a_row)*KC_ + k0 + a_col];
        As[a_col+0][a_row] = av.x;
        As[a_col+1][a_row] = av.y;
        As[a_col+2][a_row] = av.z;
        As[a_col+3][a_row] = av.w;

        int kr = k0 + b_row;
        int ci = kr / 3;
        int ko = kr - 3*ci;                       // 0..2
        const float* xrow = xb + (size_t)ci * L_;
        int gbase = l0 + b_col + ko - 1;
        #pragma unroll
        for (int jj = 0; jj < 4; jj++) {
            int gl = gbase + jj;
            Bs[b_row][b_col + jj] = ((unsigned)gl < (unsigned)L_) ? __ldg(&xrow[gl]) : 0.f;
        }
        __syncthreads();
        #pragma unroll
        for (int kk = 0; kk < GK; kk++) {
            float ar[8], br[8];
            *(float4*)&ar[0] = *(const float4*)&As[kk][ty*8];
            *(float4*)&ar[4] = *(const float4*)&As[kk][ty*8+4];
            *(float4*)&br[0] = *(const float4*)&Bs[kk][tx*8];
            *(float4*)&br[4] = *(const float4*)&Bs[kk][tx*8+4];
            #pragma unroll
            for (int i = 0; i < 8; i++)
                #pragma unroll
                for (int j = 0; j < 8; j++)
                    acc[i][j] += ar[i]*br[j];
        }
        __syncthreads();
    }

    // BN (+relu) epilogue
    float vals[8][8];
    #pragma unroll
    for (int i = 0; i < 8; i++) {
        int co = m0 + ty*8 + i;
        float scale = bng[co] * rsqrtf(bnv[co] + 1e-5f);
        float shift = bnb[co] - bnm[co]*scale;
        #pragma unroll
        for (int j = 0; j < 8; j++) {
            float v = acc[i][j]*scale + shift;
            if (do_relu) v = fmaxf(v, 0.f);
            vals[i][j] = v;
        }
    }
    if (!transpose_out) {
        #pragma unroll
        for (int i = 0; i < 8; i++) {
            size_t base = ((size_t)b*C_ + m0 + ty*8 + i)*L_ + l0 + tx*8;
            *(float4*)&Y[base]   = make_float4(vals[i][0], vals[i][1], vals[i][2], vals[i][3]);
            *(float4*)&Y[base+4] = make_float4(vals[i][4], vals[i][5], vals[i][6], vals[i][7]);
        }
    } else {
        #pragma unroll
        for (int j = 0; j < 8; j++) {
            int l = l0 + tx*8 + j;
            size_t base = ((size_t)b*L_ + l)*C_ + m0 + ty*8;
            *(float4*)&Y[base]   = make_float4(vals[0][j], vals[1][j], vals[2][j], vals[3][j]);
            *(float4*)&Y[base+4] = make_float4(vals[4][j], vals[5][j], vals[6][j], vals[7][j]);
        }
    }
}

// ---------------- SGEMM 128x128x8, 8x8 per thread, fused epilogue ----------
// (round-1 version: measured 78 TF/s, fma pipe ~49% = ceiling)
__global__ void sgemm_kernel(const float* __restrict__ A, const float* __restrict__ B,
                             float* __restrict__ C, int M, int N, int K, int epi) {
    __shared__ __align__(16) float As[GK][GM];
    __shared__ __align__(16) float Bs[GK][GN];
    int tid = threadIdx.x;            // 256
    size_t m0 = (size_t)blockIdx.y * GM;
    size_t n0 = (size_t)blockIdx.x * GN;
    int tx = tid & 15, ty = tid >> 4;

    float acc[8][8] = {};
    int a_row = tid >> 1;
    int a_col = (tid & 1) * 4;
    int b_row = tid >> 5;
    int b_col = (tid & 31) * 4;

    for (int k0 = 0; k0 < K; k0 += GK) {
        float4 av = *(const float4*)&A[(m0 + a_row)*K + k0 + a_col];
        As[a_col+0][a_row] = av.x;
        As[a_col+1][a_row] = av.y;
        As[a_col+2][a_row] = av.z;
        As[a_col+3][a_row] = av.w;
        *(float4*)&Bs[b_row][b_col] = *(const float4*)&B[(size_t)(k0 + b_row)*N + n0 + b_col];
        __syncthreads();
        #pragma unroll
        for (int kk = 0; kk < GK; kk++) {
            float ar[8], br[8];
            *(float4*)&ar[0] = *(const float4*)&As[kk][ty*8];
            *(float4*)&ar[4] = *(const float4*)&As[kk][ty*8+4];
            *(float4*)&br[0] = *(const float4*)&Bs[kk][tx*8];
            *(float4*)&br[4] = *(const float4*)&Bs[kk][tx*8+4];
            #pragma unroll
            for (int i = 0; i < 8; i++)
                #pragma unroll
                for (int j = 0; j < 8; j++)
                    acc[i][j] += ar[i]*br[j];
        }
        __syncthreads();
    }
    #pragma unroll
    for (int i = 0; i < 8; i++) {
        size_t row = m0 + ty*8 + i;
        #pragma unroll
        for (int j0 = 0; j0 < 8; j0 += 4) {
            float t[4];
            #pragma unroll
            for (int j = 0; j < 4; j++) {
                float u = acc[i][j0+j];
                if (epi == 1) u = fmaxf(u, 0.f);
                else if (epi == 2) u = 1.f/(1.f + expf(-u));
                t[j] = u;
            }
            *(float4*)&C[row*N + n0 + tx*8 + j0] = make_float4(t[0], t[1], t[2], t[3]);
        }
    }
}

// ---------------- LayerNorm over last dim (C_=256), in-place ---------------
__global__ void ln_kernel(float* __restrict__ data,
                          const float* __restrict__ g, const float* __restrict__ b) {
    __shared__ float sh[8];
    size_t row = blockIdx.x;
    float* p = data + row * C_;
    int t = threadIdx.x;      // 256
    int lane = t & 31, wid = t >> 5;
    float v = p[t];

    float s = v;
    #pragma unroll
    for (int o = 16; o; o >>= 1) s += __shfl_xor_sync(0xffffffffu, s, o);
    if (lane == 0) sh[wid] = s;
    __syncthreads();
    if (wid == 0) {
        float r = (lane < 8) ? sh[lane] : 0.f;
        #pragma unroll
        for (int o = 4; o; o >>= 1) r += __shfl_xor_sync(0xffffffffu, r, o);
        if (lane == 0) sh[0] = r;
    }
    __syncthreads();
    float mean = sh[0] * (1.f / C_);
    __syncthreads();

    float d = v - mean;
    float s2 = d * d;
    #pragma unroll
    for (int o = 16; o; o >>= 1) s2 += __shfl_xor_sync(0xffffffffu, s2, o);
    if (lane == 0) sh[wid] = s2;
    __syncthreads();
    if (wid == 0) {
        float r = (lane < 8) ? sh[lane] : 0.f;
        #pragma unroll
        for (int o = 4; o; o >>= 1) r += __shfl_xor_sync(0xffffffffu, r, o);
        if (lane == 0) sh[0] = r;
    }
    __syncthreads();
    float var = sh[0] * (1.f / C_);
    p[t] = d * rsqrtf(var + 1e-6f) * g[t] + b[t];
}

// ------- final: out[b,c,l] = relu(xp[b,l,c]*fw[b,l,c] + x[b,c,l]) ----------
__global__ void final_kernel(const float* __restrict__ xp, const float* __restrict__ fw,
                             const float* __restrict__ x, float* __restrict__ out) {
    __shared__ float tile[32][33];
    int b  = blockIdx.z;
    int c0 = blockIdx.x * 32;
    int l0 = blockIdx.y * 32;
    int tx = threadIdx.x, ty = threadIdx.y;   // 32 x 8
    #pragma unroll
    for (int i = 0; i < 32; i += 8) {
        int l = l0 + ty + i;
        size_t idx = ((size_t)b*L_ + l)*C_ + c0 + tx;
        tile[ty+i][tx] = xp[idx] * fw[idx];
    }
    __syncthreads();
    #pragma unroll
    for (int i = 0; i < 32; i += 8) {
        int c = c0 + ty + i;
        int l = l0 + tx;
        size_t idx = ((size_t)b*C_ + c)*L_ + l;
        out[idx] = fmaxf(tile[tx][ty+i] + x[idx], 0.f);
    }
}

// ---------------------------------------------------------------------------
extern "C" void kernel_launch(void* const* d_in, const int* in_sizes, int n_in,
                              void* d_out, int out_size) {
    const float* x       = (const float*)d_in[0];
    const float* conv1_w = (const float*)d_in[1];
    const float* bn1_g   = (const float*)d_in[2];
    const float* bn1_b   = (const float*)d_in[3];
    const float* bn1_m   = (const float*)d_in[4];
    const float* bn1_v   = (const float*)d_in[5];
    const float* conv2_w = (const float*)d_in[6];
    const float* bn2_g   = (const float*)d_in[7];
    const float* bn2_b   = (const float*)d_in[8];
    const float* bn2_m   = (const float*)d_in[9];
    const float* bn2_v   = (const float*)d_in[10];
    const float* fc1_w   = (const float*)d_in[11];
    const float* fc2_w   = (const float*)d_in[12];
    const float* ln_g    = (const float*)d_in[13];
    const float* ln_b    = (const float*)d_in[14];
    float* out = (float*)d_out;

    float *y1, *xp, *t1, *h, *dct, *fc1t, *fc2t;
    cudaGetSymbolAddress((void**)&y1,   g_y1);
    cudaGetSymbolAddress((void**)&xp,   g_xp);
    cudaGetSymbolAddress((void**)&t1,   g_t1);
    cudaGetSymbolAddress((void**)&h,    g_h);
    cudaGetSymbolAddress((void**)&dct,  g_dct);
    cudaGetSymbolAddress((void**)&fc1t, g_fc1t);
    cudaGetSymbolAddress((void**)&fc2t, g_fc2t);

    // 0. precompute DCT matrix + transposed weights
    precompute_kernel<<<(C_*H_ + 255)/256, 256>>>(fc1_w, fc2_w);

    // 1. conv1 + bn1 + relu -> y1 [B,C,L]   (conv as M=256,N=4096,K=768 GEMM)
    {
        dim3 grid(L_/GN, C_/GM, B_);
        conv_gemm_kernel<<<grid, 256>>>(x, conv1_w, bn1_g, bn1_b, bn1_m, bn1_v,
                                        y1, /*relu=*/1, /*transpose=*/0);
    }
    // 2. conv2 + bn2 -> xp [B,L,C] (transposed)
    {
        dim3 grid(L_/GN, C_/GM, B_);
        conv_gemm_kernel<<<grid, 256>>>(y1, conv2_w, bn2_g, bn2_b, bn2_m, bn2_v,
                                        xp, /*relu=*/0, /*transpose=*/1);
    }
    // 3. freq = xp @ Dm^T  -> t1 [BL, C]
    {
        dim3 grid(C_/GN, BL_/GM);
        sgemm_kernel<<<grid, 256>>>(xp, dct, t1, BL_, C_, C_, /*epi=*/0);
    }
    // 4. sd = LN(freq), in place
    ln_kernel<<<BL_, C_>>>(t1, ln_g, ln_b);

    // 5. h = relu(sd @ fc1^T) -> g_h [BL, 2C]
    {
        dim3 grid(H_/GN, BL_/GM);
        sgemm_kernel<<<grid, 256>>>(t1, fc1t, h, BL_, H_, C_, /*epi=*/1);
    }
    // 6. fw = sigmoid(h @ fc2^T) -> t1 [BL, C]
    {
        dim3 grid(C_/GN, BL_/GM);
        sgemm_kernel<<<grid, 256>>>(h, fc2t, t1, BL_, C_, H_, /*epi=*/2);
    }
    // 7. fw = LN(fw), in place
    ln_kernel<<<BL_, C_>>>(t1, ln_g, ln_b);

    // 8. out = relu(transpose(xp * fw) + x)
    {
        dim3 grid(C_/32, L_/32, B_);
        final_kernel<<<grid, dim3(32, 8)>>>(xp, t1, x, out);
    }
}

// round 4
// speedup vs baseline: 1.3759x; 1.1304x over previous
#include <cuda_runtime.h>
#include <math.h>

#define B_ 32
#define C_ 256
#define L_ 4096
#define H_ (2*C_)
#define BL_ (B_*L_)
#define KC_ (3*C_)   // 768

// ---------------- scratch (device globals; no allocation allowed) ----------
__device__ float g_y1[(size_t)B_*C_*L_];   // conv1 output [B,C,L]
__device__ float g_xp[(size_t)B_*L_*C_];   // conv2 output transposed [B,L,C]
__device__ float g_t1[(size_t)B_*L_*C_];   // freq / sd / fw  [B*L, C]
__device__ float g_h [(size_t)B_*L_*H_];   // hidden [B*L, 2C]
__device__ float g_dct [C_*C_];            // [n][k] = Dm[k][n]
__device__ float g_fc1t[C_*H_];            // [c][j] = fc1_w[j][c]
__device__ float g_fc2t[H_*C_];            // [j][c] = fc2_w[c][j]

// ---------------- precompute: DCT matrix + transposed fc weights -----------
__global__ void precompute_kernel(const float* __restrict__ fc1_w,
                                  const float* __restrict__ fc2_w) {
    int idx = blockIdx.x * blockDim.x + threadIdx.x;
    if (idx < C_*C_) {
        int n = idx / C_, k = idx % C_;
        double v = 2.0 * cos(M_PI * (double)k * (2.0*n + 1.0) / (2.0 * C_));
        g_dct[n*C_ + k] = (float)v;
    }
    if (idx < C_*H_) {
        int c = idx / H_, j = idx % H_;
        g_fc1t[c*H_ + j] = fc1_w[j*C_ + c];   // fc1_w: [2C, C]
        g_fc2t[j*C_ + c] = fc2_w[c*H_ + j];   // fc2_w: [C, 2C]
    }
}

#define GM 128
#define GN 128
#define GK 8

// ===== conv1d(K=3,pad=1)+BN(+relu): 128(co) x 128(l) tile, 8 ci per step ===
// One shared X tile [8][136] (halo +-4, aligned float4 loads) serves all
// three kernel taps; inner loop does 3 rank-1 updates per ci (192 FMA).
__global__ void conv3_kernel(const float* __restrict__ X,
                             const float* __restrict__ W,
                             const float* __restrict__ bng, const float* __restrict__ bnb,
                             const float* __restrict__ bnm, const float* __restrict__ bnv,
                             float* __restrict__ Y, int do_relu, int transpose_out) {
    __shared__ __align__(16) float As[3][GK][GM];   // [k][ci][co]
    __shared__ __align__(16) float Bs[GK][136];     // col c <-> l = l0 + c - 4
    int b  = blockIdx.z;
    int m0 = blockIdx.y * GM;   // co
    int l0 = blockIdx.x * GN;   // l
    int tid = threadIdx.x;      // 256
    int tx = tid & 15, ty = tid >> 4;
    const float* xb = X + (size_t)b * C_ * L_;

    float acc[8][8] = {};
    int a_row  = tid >> 1;      // 0..127 (co within tile)
    int a_half = tid & 1;       // each half loads 12 consecutive W floats

    for (int ci0 = 0; ci0 < C_; ci0 += GK) {
        // --- A tile: W[m0+a_row][ci0*3 + a_half*12 .. +12), de-interleave (ci,k)
        {
            const float* wp = W + (size_t)(m0 + a_row)*KC_ + ci0*3 + a_half*12;
            #pragma unroll
            for (int v = 0; v < 3; v++) {
                float4 w4 = *(const float4*)(wp + v*4);
                int t = a_half*12 + v*4;
                As[(t+0)%3][(t+0)/3][a_row] = w4.x;
                As[(t+1)%3][(t+1)/3][a_row] = w4.y;
                As[(t+2)%3][(t+2)/3][a_row] = w4.z;
                As[(t+3)%3][(t+3)/3][a_row] = w4.w;
            }
        }
        // --- B tile: 8 rows x 34 float4 (cols 0..135 <-> l0-4..l0+131)
        #pragma unroll
        for (int it = 0; it < 2; it++) {
            int i = tid + it*256;
            if (i < 8*34) {
                int r = i / 34, c4 = i % 34;
                int gl = l0 + c4*4 - 4;
                float4 v;
                if (gl >= 0 && gl + 4 <= L_)
                    v = *(const float4*)(xb + (size_t)(ci0 + r)*L_ + gl);
                else
                    v = make_float4(0.f, 0.f, 0.f, 0.f);   // all-or-nothing at edges
                *(float4*)&Bs[r][c4*4] = v;
            }
        }
        __syncthreads();

        #pragma unroll
        for (int kk = 0; kk < GK; kk++) {
            float br[10];
            #pragma unroll
            for (int q = 0; q < 10; q++) br[q] = Bs[kk][tx*8 + 3 + q];
            #pragma unroll
            for (int k = 0; k < 3; k++) {
                float ar[8];
                *(float4*)&ar[0] = *(const float4*)&As[k][kk][ty*8];
                *(float4*)&ar[4] = *(const float4*)&As[k][kk][ty*8+4];
                #pragma unroll
                for (int i = 0; i < 8; i++)
                    #pragma unroll
                    for (int j = 0; j < 8; j++)
                        acc[i][j] += ar[i] * br[j + k];
            }
        }
        __syncthreads();
    }

    // --- BN (+relu) epilogue
    float vals[8][8];
    #pragma unroll
    for (int i = 0; i < 8; i++) {
        int co = m0 + ty*8 + i;
        float scale = bng[co] * rsqrtf(bnv[co] + 1e-5f);
        float shift = bnb[co] - bnm[co]*scale;
        #pragma unroll
        for (int j = 0; j < 8; j++) {
            float v = acc[i][j]*scale + shift;
            if (do_relu) v = fmaxf(v, 0.f);
            vals[i][j] = v;
        }
    }
    if (!transpose_out) {
        #pragma unroll
        for (int i = 0; i < 8; i++) {
            size_t base = ((size_t)b*C_ + m0 + ty*8 + i)*L_ + l0 + tx*8;
            *(float4*)&Y[base]   = make_float4(vals[i][0], vals[i][1], vals[i][2], vals[i][3]);
            *(float4*)&Y[base+4] = make_float4(vals[i][4], vals[i][5], vals[i][6], vals[i][7]);
        }
    } else {
        #pragma unroll
        for (int j = 0; j < 8; j++) {
            int l = l0 + tx*8 + j;
            size_t base = ((size_t)b*L_ + l)*C_ + m0 + ty*8;
            *(float4*)&Y[base]   = make_float4(vals[0][j], vals[1][j], vals[2][j], vals[3][j]);
            *(float4*)&Y[base+4] = make_float4(vals[4][j], vals[5][j], vals[6][j], vals[7][j]);
        }
    }
}

// ---------------- SGEMM 128x128x8, 8x8 per thread, fused epilogue ----------
// (round-1 version: measured 78 TF/s, fma pipe ~49% = ceiling)
__global__ void sgemm_kernel(const float* __restrict__ A, const float* __restrict__ B,
                             float* __restrict__ C, int M, int N, int K, int epi) {
    __shared__ __align__(16) float As[GK][GM];
    __shared__ __align__(16) float Bs[GK][GN];
    int tid = threadIdx.x;            // 256
    size_t m0 = (size_t)blockIdx.y * GM;
    size_t n0 = (size_t)blockIdx.x * GN;
    int tx = tid & 15, ty = tid >> 4;

    float acc[8][8] = {};
    int a_row = tid >> 1;
    int a_col = (tid & 1) * 4;
    int b_row = tid >> 5;
    int b_col = (tid & 31) * 4;

    for (int k0 = 0; k0 < K; k0 += GK) {
        float4 av = *(const float4*)&A[(m0 + a_row)*K + k0 + a_col];
        As[a_col+0][a_row] = av.x;
        As[a_col+1][a_row] = av.y;
        As[a_col+2][a_row] = av.z;
        As[a_col+3][a_row] = av.w;
        *(float4*)&Bs[b_row][b_col] = *(const float4*)&B[(size_t)(k0 + b_row)*N + n0 + b_col];
        __syncthreads();
        #pragma unroll
        for (int kk = 0; kk < GK; kk++) {
            float ar[8], br[8];
            *(float4*)&ar[0] = *(const float4*)&As[kk][ty*8];
            *(float4*)&ar[4] = *(const float4*)&As[kk][ty*8+4];
            *(float4*)&br[0] = *(const float4*)&Bs[kk][tx*8];
            *(float4*)&br[4] = *(const float4*)&Bs[kk][tx*8+4];
            #pragma unroll
            for (int i = 0; i < 8; i++)
                #pragma unroll
                for (int j = 0; j < 8; j++)
                    acc[i][j] += ar[i]*br[j];
        }
        __syncthreads();
    }
    #pragma unroll
    for (int i = 0; i < 8; i++) {
        size_t row = m0 + ty*8 + i;
        #pragma unroll
        for (int j0 = 0; j0 < 8; j0 += 4) {
            float t[4];
            #pragma unroll
            for (int j = 0; j < 4; j++) {
                float u = acc[i][j0+j];
                if (epi == 1) u = fmaxf(u, 0.f);
                else if (epi == 2) u = 1.f/(1.f + expf(-u));
                t[j] = u;
            }
            *(float4*)&C[row*N + n0 + tx*8 + j0] = make_float4(t[0], t[1], t[2], t[3]);
        }
    }
}

// ---------------- LayerNorm over last dim (C_=256), in-place ---------------
__global__ void ln_kernel(float* __restrict__ data,
                          const float* __restrict__ g, const float* __restrict__ b) {
    __shared__ float sh[8];
    size_t row = blockIdx.x;
    float* p = data + row * C_;
    int t = threadIdx.x;      // 256
    int lane = t & 31, wid = t >> 5;
    float v = p[t];

    float s = v;
    #pragma unroll
    for (int o = 16; o; o >>= 1) s += __shfl_xor_sync(0xffffffffu, s, o);
    if (lane == 0) sh[wid] = s;
    __syncthreads();
    if (wid == 0) {
        float r = (lane < 8) ? sh[lane] : 0.f;
        #pragma unroll
        for (int o = 4; o; o >>= 1) r += __shfl_xor_sync(0xffffffffu, r, o);
        if (lane == 0) sh[0] = r;
    }
    __syncthreads();
    float mean = sh[0] * (1.f / C_);
    __syncthreads();

    float d = v - mean;
    float s2 = d * d;
    #pragma unroll
    for (int o = 16; o; o >>= 1) s2 += __shfl_xor_sync(0xffffffffu, s2, o);
    if (lane == 0) sh[wid] = s2;
    __syncthreads();
    if (wid == 0) {
        float r = (lane < 8) ? sh[lane] : 0.f;
        #pragma unroll
        for (int o = 4; o; o >>= 1) r += __shfl_xor_sync(0xffffffffu, r, o);
        if (lane == 0) sh[0] = r;
    }
    __syncthreads();
    float var = sh[0] * (1.f / C_);
    p[t] = d * rsqrtf(var + 1e-6f) * g[t] + b[t];
}

// ------- final: out[b,c,l] = relu(xp[b,l,c]*fw[b,l,c] + x[b,c,l]) ----------
__global__ void final_kernel(const float* __restrict__ xp, const float* __restrict__ fw,
                             const float* __restrict__ x, float* __restrict__ out) {
    __shared__ float tile[32][33];
    int b  = blockIdx.z;
    int c0 = blockIdx.x * 32;
    int l0 = blockIdx.y * 32;
    int tx = threadIdx.x, ty = threadIdx.y;   // 32 x 8
    #pragma unroll
    for (int i = 0; i < 32; i += 8) {
        int l = l0 + ty + i;
        size_t idx = ((size_t)b*L_ + l)*C_ + c0 + tx;
        tile[ty+i][tx] = xp[idx] * fw[idx];
    }
    __syncthreads();
    #pragma unroll
    for (int i = 0; i < 32; i += 8) {
        int c = c0 + ty + i;
        int l = l0 + tx;
        size_t idx = ((size_t)b*C_ + c)*L_ + l;
        out[idx] = fmaxf(tile[tx][ty+i] + x[idx], 0.f);
    }
}

// ---------------------------------------------------------------------------
extern "C" void kernel_launch(void* const* d_in, const int* in_sizes, int n_in,
                              void* d_out, int out_size) {
    const float* x       = (const float*)d_in[0];
    const float* conv1_w = (const float*)d_in[1];
    const float* bn1_g   = (const float*)d_in[2];
    const float* bn1_b   = (const float*)d_in[3];
    const float* bn1_m   = (const float*)d_in[4];
    const float* bn1_v   = (const float*)d_in[5];
    const float* conv2_w = (const float*)d_in[6];
    const float* bn2_g   = (const float*)d_in[7];
    const float* bn2_b   = (const float*)d_in[8];
    const float* bn2_m   = (const float*)d_in[9];
    const float* bn2_v   = (const float*)d_in[10];
    const float* fc1_w   = (const float*)d_in[11];
    const float* fc2_w   = (const float*)d_in[12];
    const float* ln_g    = (const float*)d_in[13];
    const float* ln_b    = (const float*)d_in[14];
    float* out = (float*)d_out;

    float *y1, *xp, *t1, *h, *dct, *fc1t, *fc2t;
    cudaGetSymbolAddress((void**)&y1,   g_y1);
    cudaGetSymbolAddress((void**)&xp,   g_xp);
    cudaGetSymbolAddress((void**)&t1,   g_t1);
    cudaGetSymbolAddress((void**)&h,    g_h);
    cudaGetSymbolAddress((void**)&dct,  g_dct);
    cudaGetSymbolAddress((void**)&fc1t, g_fc1t);
    cudaGetSymbolAddress((void**)&fc2t, g_fc2t);

    // 0. precompute DCT matrix + transposed weights
    precompute_kernel<<<(C_*H_ + 255)/256, 256>>>(fc1_w, fc2_w);

    // 1. conv1 + bn1 + relu -> y1 [B,C,L]
    {
        dim3 grid(L_/GN, C_/GM, B_);
        conv3_kernel<<<grid, 256>>>(x, conv1_w, bn1_g, bn1_b, bn1_m, bn1_v,
                                    y1, /*relu=*/1, /*transpose=*/0);
    }
    // 2. conv2 + bn2 -> xp [B,L,C] (transposed)
    {
        dim3 grid(L_/GN, C_/GM, B_);
        conv3_kernel<<<grid, 256>>>(y1, conv2_w, bn2_g, bn2_b, bn2_m, bn2_v,
                                    xp, /*relu=*/0, /*transpose=*/1);
    }
    // 3. freq = xp @ Dm^T  -> t1 [BL, C]
    {
        dim3 grid(C_/GN, BL_/GM);
        sgemm_kernel<<<grid, 256>>>(xp, dct, t1, BL_, C_, C_, /*epi=*/0);
    }
    // 4. sd = LN(freq), in place
    ln_kernel<<<BL_, C_>>>(t1, ln_g, ln_b);

    // 5. h = relu(sd @ fc1^T) -> g_h [BL, 2C]
    {
        dim3 grid(H_/GN, BL_/GM);
        sgemm_kernel<<<grid, 256>>>(t1, fc1t, h, BL_, H_, C_, /*epi=*/1);
    }
    // 6. fw = sigmoid(h @ fc2^T) -> t1 [BL, C]
    {
        dim3 grid(C_/GN, BL_/GM);
        sgemm_kernel<<<grid, 256>>>(h, fc2t, t1, BL_, C_, H_, /*epi=*/2);
    }
    // 7. fw = LN(fw), in place
    ln_kernel<<<BL_, C_>>>(t1, ln_g, ln_b);

    // 8. out = relu(transpose(xp * fw) + x)
    {
        dim3 grid(C_/32, L_/32, B_);
        final_kernel<<<grid, dim3(32, 8)>>>(xp, t1, x, out);
    }
}

// round 5
// speedup vs baseline: 3.6057x; 2.6206x over previous
#include <cuda_runtime.h>
#include <math.h>
#include <stdint.h>

#define B_ 32
#define C_ 256
#define L_ 4096
#define H_ (2*C_)
#define BL_ (B_*L_)

// ---------------- scratch (device globals; no allocation allowed) ----------
__device__ float g_y1[(size_t)B_*C_*L_];   // conv1 output [B,C,L]
__device__ float g_xp[(size_t)B_*L_*C_];   // conv2 output transposed [B,L,C]
__device__ float g_t1[(size_t)B_*L_*C_];   // freq / sd / fw  [B*L, C]
__device__ float g_h [(size_t)B_*L_*H_];   // hidden [B*L, 2C]
__device__ float g_dct [C_*C_];            // [n][k] tf32-rounded
__device__ float g_fc1t[C_*H_];            // [c][j] tf32-rounded
__device__ float g_fc2t[H_*C_];            // [j][c] tf32-rounded
__device__ float g_w1p[3*C_*C_];           // [k][co][ci] tf32-rounded
__device__ float g_w2p[3*C_*C_];           // [k][co][ci] tf32-rounded

// ---------------- tf32 helpers ---------------------------------------------
__device__ __forceinline__ uint32_t f2tf(float f) {
    uint32_t u; asm("cvt.rna.tf32.f32 %0, %1;" : "=r"(u) : "f"(f)); return u;
}
__device__ __forceinline__ void mma_tf32(float c[4],
        uint32_t a0, uint32_t a1, uint32_t a2, uint32_t a3,
        uint32_t b0, uint32_t b1) {
    asm volatile(
        "mma.sync.aligned.m16n8k8.row.col.f32.tf32.tf32.f32 "
        "{%0,%1,%2,%3}, {%4,%5,%6,%7}, {%8,%9}, {%0,%1,%2,%3};"
        : "+f"(c[0]), "+f"(c[1]), "+f"(c[2]), "+f"(c[3])
        : "r"(a0), "r"(a1), "r"(a2), "r"(a3), "r"(b0), "r"(b1));
}

// ---------------- precompute: DCT + transposed fcs + conv planes (tf32) ----
__global__ void precompute_kernel(const float* __restrict__ fc1_w,
                                  const float* __restrict__ fc2_w,
                                  const float* __restrict__ w1,
                                  const float* __restrict__ w2) {
    int idx = blockIdx.x * blockDim.x + threadIdx.x;
    if (idx < C_*C_) {
        int n = idx / C_, k = idx % C_;
        double v = 2.0 * cos(M_PI * (double)k * (2.0*n + 1.0) / (2.0 * C_));
        g_dct[n*C_ + k] = __uint_as_float(f2tf((float)v));
    }
    if (idx < C_*H_) {
        int c1 = idx / H_, j1 = idx % H_;
        g_fc1t[c1*H_ + j1] = __uint_as_float(f2tf(fc1_w[j1*C_ + c1]));
        int j2 = idx / C_, c2 = idx % C_;
        g_fc2t[j2*C_ + c2] = __uint_as_float(f2tf(fc2_w[c2*H_ + j2]));
    }
    if (idx < 3*C_*C_) {
        int p = idx / (C_*C_);
        int rem = idx % (C_*C_);
        int co = rem / C_, ci = rem % C_;
        g_w1p[idx] = __uint_as_float(f2tf(w1[(size_t)co*3*C_ + ci*3 + p]));
        g_w2p[idx] = __uint_as_float(f2tf(w2[(size_t)co*3*C_ + ci*3 + p]));
    }
}

// ================= TF32 tensor-core SGEMM: 128x128x32 per CTA ==============
// C[M,N] = A[M,K] @ B[K,N].  A fp32 (cvt at load), B pre-rounded tf32 bits.
// 256 threads = 8 warps (2 m x 4 n), warp tile 64x32 via m16n8k8.
#define AS_LD 36
#define BS_LD 136

__global__ void sgemm_tc(const float* __restrict__ A, const uint32_t* __restrict__ Btf,
                         float* __restrict__ Cout, int M, int N, int K, int epi) {
    __shared__ __align__(16) uint32_t As[128][AS_LD];
    __shared__ __align__(16) uint32_t Bs[32][BS_LD];
    int tid = threadIdx.x, lane = tid & 31, wid = tid >> 5;
    int wm = (wid & 1) * 64, wn = (wid >> 1) * 32;
    int g = lane >> 2, tg = lane & 3;
    size_t m0 = (size_t)blockIdx.y * 128, n0 = (size_t)blockIdx.x * 128;

    float acc[4][4][4] = {};

    for (int k0 = 0; k0 < K; k0 += 32) {
        #pragma unroll
        for (int i = 0; i < 4; i++) {
            int id = tid + i*256;
            int r = id >> 3, c4 = (id & 7) * 4;
            float4 v = *(const float4*)&A[(m0 + r)*K + k0 + c4];
            uint4 u = make_uint4(f2tf(v.x), f2tf(v.y), f2tf(v.z), f2tf(v.w));
            *(uint4*)&As[r][c4] = u;
        }
        #pragma unroll
        for (int i = 0; i < 4; i++) {
            int id = tid + i*256;
            int r = id >> 5, c4 = (id & 31) * 4;
            *(uint4*)&Bs[r][c4] = *(const uint4*)&Btf[(size_t)(k0 + r)*N + n0 + c4];
        }
        __syncthreads();
        #pragma unroll
        for (int ks = 0; ks < 4; ks++) {
            int kb = ks * 8;
            uint32_t af[4][4], bf[4][2];
            #pragma unroll
            for (int mt = 0; mt < 4; mt++) {
                int r = wm + mt*16 + g;
                af[mt][0] = As[r][kb+tg];     af[mt][1] = As[r+8][kb+tg];
                af[mt][2] = As[r][kb+tg+4];   af[mt][3] = As[r+8][kb+tg+4];
            }
            #pragma unroll
            for (int nt = 0; nt < 4; nt++) {
                int c = wn + nt*8 + g;
                bf[nt][0] = Bs[kb+tg][c];     bf[nt][1] = Bs[kb+tg+4][c];
            }
            #pragma unroll
            for (int mt = 0; mt < 4; mt++)
                #pragma unroll
                for (int nt = 0; nt < 4; nt++)
                    mma_tf32(acc[mt][nt], af[mt][0], af[mt][1], af[mt][2], af[mt][3],
                             bf[nt][0], bf[nt][1]);
        }
        __syncthreads();
    }
    #pragma unroll
    for (int mt = 0; mt < 4; mt++)
        #pragma unroll
        for (int nt = 0; nt < 4; nt++)
            #pragma unroll
            for (int h = 0; h < 2; h++) {
                size_t row = m0 + wm + mt*16 + g + h*8;
                size_t col = n0 + wn + nt*8 + tg*2;
                float v0 = acc[mt][nt][h*2+0], v1 = acc[mt][nt][h*2+1];
                if (epi == 1) { v0 = fmaxf(v0, 0.f); v1 = fmaxf(v1, 0.f); }
                else if (epi == 2) { v0 = 1.f/(1.f+expf(-v0)); v1 = 1.f/(1.f+expf(-v1)); }
                *(float2*)&Cout[row*N + col] = make_float2(v0, v1);
            }
}

// ====== TF32 conv1d(K=3,pad=1)+BN(+relu): 3 shifted GEMMs, one halo tile ===
// Wp = [3][C][C] tf32 planes. B tile: X rows ci (16), cols l0-4 .. l0+131.
#define CAS_LD 20
#define CBS_LD 136
#define CONV_SMEM (3*128*CAS_LD*4 + 16*CBS_LD*4)   // 30720 + 8704 = 39424

__global__ void conv_tc(const float* __restrict__ X, const float* __restrict__ Wp,
                        const float* __restrict__ bng, const float* __restrict__ bnb,
                        const float* __restrict__ bnm, const float* __restrict__ bnv,
                        float* __restrict__ Y, int do_relu, int transpose_out) {
    __shared__ __align__(16) unsigned char csm[CONV_SMEM];
    uint32_t (*As3)[128][CAS_LD] = reinterpret_cast<uint32_t(*)[128][CAS_LD]>(csm);
    uint32_t (*Bs)[CBS_LD]       = reinterpret_cast<uint32_t(*)[CBS_LD]>(csm + 3*128*CAS_LD*4);

    int tid = threadIdx.x, lane = tid & 31, wid = tid >> 5;
    int b = blockIdx.z, m0 = blockIdx.y * 128, l0 = blockIdx.x * 128;
    int wm = (wid & 1) * 64;
    int warp_n = wid >> 1;
    int wn = warp_n * 32;
    int g = lane >> 2, tg = lane & 3;
    const float* xb = X + (size_t)b * C_ * L_;
    const uint32_t* WpU = (const uint32_t*)Wp;

    float acc[4][4][4] = {};

    for (int ci0 = 0; ci0 < C_; ci0 += 16) {
        // A: 3 planes x 128 x 16 = 1536 uint4
        #pragma unroll
        for (int i = 0; i < 6; i++) {
            int id = tid + i*256;           // uint4 index
            int p = id >> 9;                // / 512
            int rem = id & 511;
            int r = rem >> 2, c4 = (rem & 3) * 4;
            uint4 u = *(const uint4*)&WpU[(size_t)p*C_*C_ + (size_t)(m0 + r)*C_ + ci0 + c4];
            *(uint4*)&As3[p][r][c4] = u;
        }
        // B halo: 16 x 34 uint4 (cols 0..135 <-> l = l0 + c - 4)
        #pragma unroll
        for (int i = 0; i < 3; i++) {
            int id = tid + i*256;
            if (id < 16*34) {
                int r = id / 34, c4m = id % 34;
                int gl = l0 + c4m*4 - 4;
                float4 v = make_float4(0.f, 0.f, 0.f, 0.f);
                if (gl >= 0 && gl + 4 <= L_)
                    v = *(const float4*)&xb[(size_t)(ci0 + r)*L_ + gl];
                uint4 u = make_uint4(f2tf(v.x), f2tf(v.y), f2tf(v.z), f2tf(v.w));
                *(uint4*)&Bs[r][c4m*4] = u;
            }
        }
        __syncthreads();
        #pragma unroll
        for (int ks = 0; ks < 2; ks++) {
            int kb = ks * 8;
            #pragma unroll
            for (int p = 0; p < 3; p++) {
                uint32_t af[4][4], bf[4][2];
                #pragma unroll
                for (int mt = 0; mt < 4; mt++) {
                    int r = wm + mt*16 + g;
                    af[mt][0] = As3[p][r][kb+tg];     af[mt][1] = As3[p][r+8][kb+tg];
                    af[mt][2] = As3[p][r][kb+tg+4];   af[mt][3] = As3[p][r+8][kb+tg+4];
                }
                #pragma unroll
                for (int nt = 0; nt < 4; nt++) {
                    int c = wn + nt*8 + g + 3 + p;    // l = l0 + n + p - 1
                    bf[nt][0] = Bs[kb+tg][c];         bf[nt][1] = Bs[kb+tg+4][c];
                }
                #pragma unroll
                for (int mt = 0; mt < 4; mt++)
                    #pragma unroll
                    for (int nt = 0; nt < 4; nt++)
                        mma_tf32(acc[mt][nt], af[mt][0], af[mt][1], af[mt][2], af[mt][3],
                                 bf[nt][0], bf[nt][1]);
            }
        }
        __syncthreads();
    }

    // BN (+relu) on fragments
    #pragma unroll
    for (int mt = 0; mt < 4; mt++)
        #pragma unroll
        for (int h = 0; h < 2; h++) {
            int co = m0 + wm + mt*16 + g + h*8;
            float scale = bng[co] * rsqrtf(bnv[co] + 1e-5f);
            float shift = bnb[co] - bnm[co]*scale;
            #pragma unroll
            for (int nt = 0; nt < 4; nt++) {
                float v0 = acc[mt][nt][h*2+0]*scale + shift;
                float v1 = acc[mt][nt][h*2+1]*scale + shift;
                if (do_relu) { v0 = fmaxf(v0, 0.f); v1 = fmaxf(v1, 0.f); }
                acc[mt][nt][h*2+0] = v0; acc[mt][nt][h*2+1] = v1;
            }
        }

    if (!transpose_out) {
        #pragma unroll
        for (int mt = 0; mt < 4; mt++)
            #pragma unroll
            for (int h = 0; h < 2; h++) {
                int co = m0 + wm + mt*16 + g + h*8;
                #pragma unroll
                for (int nt = 0; nt < 4; nt++) {
                    int l = l0 + wn + nt*8 + tg*2;
                    *(float2*)&Y[((size_t)b*C_ + co)*L_ + l] =
                        make_float2(acc[mt][nt][h*2+0], acc[mt][nt][h*2+1]);
                }
            }
    } else {
        // stage 64 l-rows x 128 co at a time (aliased over mainloop smem)
        float (*stage)[132] = reinterpret_cast<float(*)[132]>(csm);
        #pragma unroll
        for (int wave = 0; wave < 2; wave++) {
            if ((warp_n >> 1) == wave) {
                int lbase = wn - wave*64;
                #pragma unroll
                for (int mt = 0; mt < 4; mt++)
                    #pragma unroll
                    for (int nt = 0; nt < 4; nt++)
                        #pragma unroll
                        for (int h = 0; h < 2; h++) {
                            int ll = lbase + nt*8 + tg*2;
                            int cc = wm + mt*16 + g + h*8;
                            stage[ll][cc]   = acc[mt][nt][h*2+0];
                            stage[ll+1][cc] = acc[mt][nt][h*2+1];
                        }
            }
            __syncthreads();
            #pragma unroll
            for (int i = 0; i < 8; i++) {
                int id = tid + i*256;
                int r = id >> 5, c4 = (id & 31) * 4;
                size_t l = (size_t)l0 + wave*64 + r;
                *(float4*)&Y[((size_t)b*L_ + l)*C_ + m0 + c4] = *(const float4*)&stage[r][c4];
            }
            __syncthreads();
        }
    }
}

// ---------------- LayerNorm over last dim (C_=256), in-place ---------------
__global__ void ln_kernel(float* __restrict__ data,
                          const float* __restrict__ g, const float* __restrict__ b) {
    __shared__ float sh[8];
    size_t row = blockIdx.x;
    float* p = data + row * C_;
    int t = threadIdx.x;
    int lane = t & 31, wid = t >> 5;
    float v = p[t];

    float s = v;
    #pragma unroll
    for (int o = 16; o; o >>= 1) s += __shfl_xor_sync(0xffffffffu, s, o);
    if (lane == 0) sh[wid] = s;
    __syncthreads();
    if (wid == 0) {
        float r = (lane < 8) ? sh[lane] : 0.f;
        #pragma unroll
        for (int o = 4; o; o >>= 1) r += __shfl_xor_sync(0xffffffffu, r, o);
        if (lane == 0) sh[0] = r;
    }
    __syncthreads();
    float mean = sh[0] * (1.f / C_);
    __syncthreads();

    float d = v - mean;
    float s2 = d * d;
    #pragma unroll
    for (int o = 16; o; o >>= 1) s2 += __shfl_xor_sync(0xffffffffu, s2, o);
    if (lane == 0) sh[wid] = s2;
    __syncthreads();
    if (wid == 0) {
        float r = (lane < 8) ? sh[lane] : 0.f;
        #pragma unroll
        for (int o = 4; o; o >>= 1) r += __shfl_xor_sync(0xffffffffu, r, o);
        if (lane == 0) sh[0] = r;
    }
    __syncthreads();
    float var = sh[0] * (1.f / C_);
    p[t] = d * rsqrtf(var + 1e-6f) * g[t] + b[t];
}

// ------- final: out[b,c,l] = relu(xp[b,l,c]*fw[b,l,c] + x[b,c,l]) ----------
__global__ void final_kernel(const float* __restrict__ xp, const float* __restrict__ fw,
                             const float* __restrict__ x, float* __restrict__ out) {
    __shared__ float tile[32][33];
    int b  = blockIdx.z;
    int c0 = blockIdx.x * 32;
    int l0 = blockIdx.y * 32;
    int tx = threadIdx.x, ty = threadIdx.y;   // 32 x 8
    #pragma unroll
    for (int i = 0; i < 32; i += 8) {
        int l = l0 + ty + i;
        size_t idx = ((size_t)b*L_ + l)*C_ + c0 + tx;
        tile[ty+i][tx] = xp[idx] * fw[idx];
    }
    __syncthreads();
    #pragma unroll
    for (int i = 0; i < 32; i += 8) {
        int c = c0 + ty + i;
        int l = l0 + tx;
        size_t idx = ((size_t)b*C_ + c)*L_ + l;
        out[idx] = fmaxf(tile[tx][ty+i] + x[idx], 0.f);
    }
}

// ---------------------------------------------------------------------------
extern "C" void kernel_launch(void* const* d_in, const int* in_sizes, int n_in,
                              void* d_out, int out_size) {
    const float* x       = (const float*)d_in[0];
    const float* conv1_w = (const float*)d_in[1];
    const float* bn1_g   = (const float*)d_in[2];
    const float* bn1_b   = (const float*)d_in[3];
    const float* bn1_m   = (const float*)d_in[4];
    const float* bn1_v   = (const float*)d_in[5];
    const float* conv2_w = (const float*)d_in[6];
    const float* bn2_g   = (const float*)d_in[7];
    const float* bn2_b   = (const float*)d_in[8];
    const float* bn2_m   = (const float*)d_in[9];
    const float* bn2_v   = (const float*)d_in[10];
    const float* fc1_w   = (const float*)d_in[11];
    const float* fc2_w   = (const float*)d_in[12];
    const float* ln_g    = (const float*)d_in[13];
    const float* ln_b    = (const float*)d_in[14];
    float* out = (float*)d_out;

    float *y1, *xp, *t1, *h, *dct, *fc1t, *fc2t, *w1p, *w2p;
    cudaGetSymbolAddress((void**)&y1,   g_y1);
    cudaGetSymbolAddress((void**)&xp,   g_xp);
    cudaGetSymbolAddress((void**)&t1,   g_t1);
    cudaGetSymbolAddress((void**)&h,    g_h);
    cudaGetSymbolAddress((void**)&dct,  g_dct);
    cudaGetSymbolAddress((void**)&fc1t, g_fc1t);
    cudaGetSymbolAddress((void**)&fc2t, g_fc2t);
    cudaGetSymbolAddress((void**)&w1p,  g_w1p);
    cudaGetSymbolAddress((void**)&w2p,  g_w2p);

    // 0. precompute tf32 weights (DCT, fc transposes, conv planes)
    precompute_kernel<<<(3*C_*C_ + 255)/256, 256>>>(fc1_w, fc2_w, conv1_w, conv2_w);

    // 1. conv1 + bn1 + relu -> y1 [B,C,L]
    {
        dim3 grid(L_/128, C_/128, B_);
        conv_tc<<<grid, 256>>>(x, w1p, bn1_g, bn1_b, bn1_m, bn1_v,
                               y1, /*relu=*/1, /*transpose=*/0);
    }
    // 2. conv2 + bn2 -> xp [B,L,C] (transposed)
    {
        dim3 grid(L_/128, C_/128, B_);
        conv_tc<<<grid, 256>>>(y1, w2p, bn2_g, bn2_b, bn2_m, bn2_v,
                               xp, /*relu=*/0, /*transpose=*/1);
    }
    // 3. freq = xp @ Dm^T -> t1 [BL, C]
    {
        dim3 grid(C_/128, BL_/128);
        sgemm_tc<<<grid, 256>>>(xp, (const uint32_t*)dct, t1, BL_, C_, C_, 0);
    }
    // 4. sd = LN(freq)
    ln_kernel<<<BL_, C_>>>(t1, ln_g, ln_b);
    // 5. h = relu(sd @ fc1^T) -> [BL, 2C]
    {
        dim3 grid(H_/128, BL_/128);
        sgemm_tc<<<grid, 256>>>(t1, (const uint32_t*)fc1t, h, BL_, H_, C_, 1);
    }
    // 6. fw = sigmoid(h @ fc2^T) -> t1 [BL, C]
    {
        dim3 grid(C_/128, BL_/128);
        sgemm_tc<<<grid, 256>>>(h, (const uint32_t*)fc2t, t1, BL_, C_, H_, 2);
    }
    // 7. fw = LN(fw)
    ln_kernel<<<BL_, C_>>>(t1, ln_g, ln_b);
    // 8. out = relu(transpose(xp * fw) + x)
    {
        dim3 grid(C_/32, L_/32, B_);
        final_kernel<<<grid, dim3(32, 8)>>>(xp, t1, x, out);
    }
}

// round 6
// speedup vs baseline: 4.6759x; 1.2968x over previous
#include <cuda_runtime.h>
#include <math.h>
#include <stdint.h>

#define B_ 32
#define C_ 256
#define L_ 4096
#define H_ (2*C_)
#define BL_ (B_*L_)

// ---------------- scratch (device globals; no allocation allowed) ----------
__device__ float g_y1[(size_t)B_*C_*L_];   // conv1 out [B,C,L], tf32-rounded
__device__ float g_xp[(size_t)B_*L_*C_];   // conv2 out transposed [B,L,C], tf32-rounded
__device__ float g_t1[(size_t)B_*L_*C_];   // freq / sd / fw
__device__ float g_h [(size_t)B_*L_*H_];   // hidden [BL, 2C], tf32-rounded
__device__ float g_xtf[(size_t)B_*C_*L_];  // tf32-rounded copy of x
__device__ float g_dct [C_*C_];            // tf32
__device__ float g_fc1t[C_*H_];            // tf32
__device__ float g_fc2t[H_*C_];            // tf32
__device__ float g_w1p[3*C_*C_];           // [k][co][ci] tf32
__device__ float g_w2p[3*C_*C_];           // [k][co][ci] tf32

// ---------------- helpers ---------------------------------------------------
__device__ __forceinline__ uint32_t f2tf(float f) {
    uint32_t u; asm("cvt.rna.tf32.f32 %0, %1;" : "=r"(u) : "f"(f)); return u;
}
__device__ __forceinline__ void mma_tf32(float c[4],
        uint32_t a0, uint32_t a1, uint32_t a2, uint32_t a3,
        uint32_t b0, uint32_t b1) {
    asm volatile(
        "mma.sync.aligned.m16n8k8.row.col.f32.tf32.tf32.f32 "
        "{%0,%1,%2,%3}, {%4,%5,%6,%7}, {%8,%9}, {%0,%1,%2,%3};"
        : "+f"(c[0]), "+f"(c[1]), "+f"(c[2]), "+f"(c[3])
        : "r"(a0), "r"(a1), "r"(a2), "r"(a3), "r"(b0), "r"(b1));
}
__device__ __forceinline__ uint32_t smem_u32(const void* p) {
    return (uint32_t)__cvta_generic_to_shared(p);
}
__device__ __forceinline__ void cp16(uint32_t dst, const void* src) {
    asm volatile("cp.async.cg.shared.global [%0], [%1], 16;" :: "r"(dst), "l"(src));
}
#define CP_COMMIT() asm volatile("cp.async.commit_group;")
#define CP_WAIT0()  asm volatile("cp.async.wait_group 0;")

// ---------------- precompute: DCT + transposed fcs + conv planes (tf32) ----
__global__ void precompute_kernel(const float* __restrict__ fc1_w,
                                  const float* __restrict__ fc2_w,
                                  const float* __restrict__ w1,
                                  const float* __restrict__ w2) {
    int idx = blockIdx.x * blockDim.x + threadIdx.x;
    if (idx < C_*C_) {
        int n = idx / C_, k = idx % C_;
        double v = 2.0 * cos(M_PI * (double)k * (2.0*n + 1.0) / (2.0 * C_));
        g_dct[n*C_ + k] = __uint_as_float(f2tf((float)v));
    }
    if (idx < C_*H_) {
        int c1 = idx / H_, j1 = idx % H_;
        g_fc1t[c1*H_ + j1] = __uint_as_float(f2tf(fc1_w[j1*C_ + c1]));
        int j2 = idx / C_, c2 = idx % C_;
        g_fc2t[j2*C_ + c2] = __uint_as_float(f2tf(fc2_w[c2*H_ + j2]));
    }
    if (idx < 3*C_*C_) {
        int p = idx / (C_*C_);
        int rem = idx % (C_*C_);
        int co = rem / C_, ci = rem % C_;
        g_w1p[idx] = __uint_as_float(f2tf(w1[(size_t)co*3*C_ + ci*3 + p]));
        g_w2p[idx] = __uint_as_float(f2tf(w2[(size_t)co*3*C_ + ci*3 + p]));
    }
}

// ---------------- x -> tf32 copy (one pass) ---------------------------------
__global__ void tf32_round_kernel(const float4* __restrict__ in, uint4* __restrict__ out) {
    size_t i = (size_t)blockIdx.x * blockDim.x + threadIdx.x;
    float4 v = in[i];
    out[i] = make_uint4(f2tf(v.x), f2tf(v.y), f2tf(v.z), f2tf(v.w));
}

// ================= TF32 tensor-core GEMM, cp.async double-buffered =========
// C[M,N] = A[M,K] @ B[K,N]; A,B pre-rounded tf32 bits. 256 thr, 8 warps.
#define AS_LD 36
#define BS_LD 136
#define SGEMM_SMEM ((2*128*AS_LD + 2*32*BS_LD)*4)   // 71680

__global__ void __launch_bounds__(256, 2)
sgemm_tc(const uint32_t* __restrict__ Atf, const uint32_t* __restrict__ Btf,
         float* __restrict__ Cout, int M, int N, int K, int epi) {
    extern __shared__ uint32_t dyn[];
    uint32_t (*As)[128][AS_LD] = (uint32_t(*)[128][AS_LD])dyn;
    uint32_t (*Bs)[32][BS_LD]  = (uint32_t(*)[32][BS_LD])(dyn + 2*128*AS_LD);

    int tid = threadIdx.x, lane = tid & 31, wid = tid >> 5;
    int wm = (wid & 1) * 64, wn = (wid >> 1) * 32;
    int g = lane >> 2, tg = lane & 3;
    size_t m0 = (size_t)blockIdx.y * 128, n0 = (size_t)blockIdx.x * 128;

    float acc[4][4][4] = {};
    int nk = K >> 5;

    // tile loader (cp.async, no regs)
    auto load_tile = [&](int t, int buf) {
        int k0 = t * 32;
        #pragma unroll
        for (int i = 0; i < 4; i++) {
            int id = tid + i*256;
            int r = id >> 3, c4 = (id & 7) * 4;
            cp16(smem_u32(&As[buf][r][c4]), &Atf[(m0 + r)*(size_t)K + k0 + c4]);
        }
        #pragma unroll
        for (int i = 0; i < 4; i++) {
            int id = tid + i*256;
            int r = id >> 5, c4 = (id & 31) * 4;
            cp16(smem_u32(&Bs[buf][r][c4]), &Btf[(size_t)(k0 + r)*N + n0 + c4]);
        }
    };

    load_tile(0, 0); CP_COMMIT(); CP_WAIT0(); __syncthreads();
    int cur = 0;
    for (int t = 0; t < nk; t++) {
        if (t + 1 < nk) { load_tile(t + 1, cur ^ 1); CP_COMMIT(); }
        #pragma unroll
        for (int ks = 0; ks < 4; ks++) {
            int kb = ks * 8;
            uint32_t af[4][4], bf[4][2];
            #pragma unroll
            for (int mt = 0; mt < 4; mt++) {
                int r = wm + mt*16 + g;
                af[mt][0] = As[cur][r][kb+tg];     af[mt][1] = As[cur][r+8][kb+tg];
                af[mt][2] = As[cur][r][kb+tg+4];   af[mt][3] = As[cur][r+8][kb+tg+4];
            }
            #pragma unroll
            for (int nt = 0; nt < 4; nt++) {
                int c = wn + nt*8 + g;
                bf[nt][0] = Bs[cur][kb+tg][c];     bf[nt][1] = Bs[cur][kb+tg+4][c];
            }
            #pragma unroll
            for (int mt = 0; mt < 4; mt++)
                #pragma unroll
                for (int nt = 0; nt < 4; nt++)
                    mma_tf32(acc[mt][nt], af[mt][0], af[mt][1], af[mt][2], af[mt][3],
                             bf[nt][0], bf[nt][1]);
        }
        if (t + 1 < nk) CP_WAIT0();
        __syncthreads();
        cur ^= 1;
    }

    #pragma unroll
    for (int mt = 0; mt < 4; mt++)
        #pragma unroll
        for (int nt = 0; nt < 4; nt++)
            #pragma unroll
            for (int h = 0; h < 2; h++) {
                size_t row = m0 + wm + mt*16 + g + h*8;
                size_t col = n0 + wn + nt*8 + tg*2;
                float v0 = acc[mt][nt][h*2+0], v1 = acc[mt][nt][h*2+1];
                if (epi == 1) {        // relu + tf32-round (feeds next GEMM A)
                    v0 = __uint_as_float(f2tf(fmaxf(v0, 0.f)));
                    v1 = __uint_as_float(f2tf(fmaxf(v1, 0.f)));
                } else if (epi == 2) {
                    v0 = 1.f/(1.f+expf(-v0)); v1 = 1.f/(1.f+expf(-v1));
                }
                *(float2*)&Cout[row*N + col] = make_float2(v0, v1);
            }
}

// ====== TF32 conv1d(K=3,pad=1)+BN(+relu), cp.async double-buffered =========
#define CAS_LD 20
#define CBS_LD 136
#define CONV_SMEM ((2*3*128*CAS_LD + 2*16*CBS_LD)*4)   // 78848

__global__ void __launch_bounds__(256, 2)
conv_tc(const uint32_t* __restrict__ X, const uint32_t* __restrict__ WpU,
        const float* __restrict__ bng, const float* __restrict__ bnb,
        const float* __restrict__ bnm, const float* __restrict__ bnv,
        float* __restrict__ Y, int do_relu, int transpose_out) {
    extern __shared__ uint32_t dyn[];
    uint32_t (*As3)[3][128][CAS_LD] = (uint32_t(*)[3][128][CAS_LD])dyn;
    uint32_t (*Bs)[16][CBS_LD]      = (uint32_t(*)[16][CBS_LD])(dyn + 2*3*128*CAS_LD);

    int tid = threadIdx.x, lane = tid & 31, wid = tid >> 5;
    int b = blockIdx.z, m0 = blockIdx.y * 128, l0 = blockIdx.x * 128;
    int wm = (wid & 1) * 64;
    int warp_n = wid >> 1;
    int wn = warp_n * 32;
    int g = lane >> 2, tg = lane & 3;
    const uint32_t* xb = X + (size_t)b * C_ * L_;

    float acc[4][4][4] = {};

    auto load_tile = [&](int ci0, int buf) {
        #pragma unroll
        for (int i = 0; i < 6; i++) {
            int id = tid + i*256;
            int p = id >> 9;
            int rem = id & 511;
            int r = rem >> 2, c4 = (rem & 3) * 4;
            cp16(smem_u32(&As3[buf][p][r][c4]),
                 &WpU[(size_t)p*C_*C_ + (size_t)(m0 + r)*C_ + ci0 + c4]);
        }
        #pragma unroll
        for (int i = 0; i < 3; i++) {
            int id = tid + i*256;
            if (id < 16*34) {
                int r = id / 34, c4m = id % 34;
                int gl = l0 + c4m*4 - 4;
                if (gl >= 0 && gl + 4 <= L_)
                    cp16(smem_u32(&Bs[buf][r][c4m*4]), &xb[(size_t)(ci0 + r)*L_ + gl]);
                else
                    *(uint4*)&Bs[buf][r][c4m*4] = make_uint4(0,0,0,0);
            }
        }
    };

    load_tile(0, 0); CP_COMMIT(); CP_WAIT0(); __syncthreads();
    int cur = 0;
    for (int t = 0; t < C_/16; t++) {
        if (t + 1 < C_/16) { load_tile((t+1)*16, cur ^ 1); CP_COMMIT(); }
        #pragma unroll
        for (int ks = 0; ks < 2; ks++) {
            int kb = ks * 8;
            #pragma unroll
            for (int p = 0; p < 3; p++) {
                uint32_t af[4][4], bf[4][2];
                #pragma unroll
                for (int mt = 0; mt < 4; mt++) {
                    int r = wm + mt*16 + g;
                    af[mt][0] = As3[cur][p][r][kb+tg];     af[mt][1] = As3[cur][p][r+8][kb+tg];
                    af[mt][2] = As3[cur][p][r][kb+tg+4];   af[mt][3] = As3[cur][p][r+8][kb+tg+4];
                }
                #pragma unroll
                for (int nt = 0; nt < 4; nt++) {
                    int c = wn + nt*8 + g + 3 + p;
                    bf[nt][0] = Bs[cur][kb+tg][c];         bf[nt][1] = Bs[cur][kb+tg+4][c];
                }
                #pragma unroll
                for (int mt = 0; mt < 4; mt++)
                    #pragma unroll
                    for (int nt = 0; nt < 4; nt++)
                        mma_tf32(acc[mt][nt], af[mt][0], af[mt][1], af[mt][2], af[mt][3],
                                 bf[nt][0], bf[nt][1]);
            }
        }
        if (t + 1 < C_/16) CP_WAIT0();
        __syncthreads();
        cur ^= 1;
    }

    // BN (+relu) + tf32-round on fragments
    #pragma unroll
    for (int mt = 0; mt < 4; mt++)
        #pragma unroll
        for (int h = 0; h < 2; h++) {
            int co = m0 + wm + mt*16 + g + h*8;
            float scale = bng[co] * rsqrtf(bnv[co] + 1e-5f);
            float shift = bnb[co] - bnm[co]*scale;
            #pragma unroll
            for (int nt = 0; nt < 4; nt++) {
                float v0 = acc[mt][nt][h*2+0]*scale + shift;
                float v1 = acc[mt][nt][h*2+1]*scale + shift;
                if (do_relu) { v0 = fmaxf(v0, 0.f); v1 = fmaxf(v1, 0.f); }
                acc[mt][nt][h*2+0] = __uint_as_float(f2tf(v0));
                acc[mt][nt][h*2+1] = __uint_as_float(f2tf(v1));
            }
        }

    if (!transpose_out) {
        #pragma unroll
        for (int mt = 0; mt < 4; mt++)
            #pragma unroll
            for (int h = 0; h < 2; h++) {
                int co = m0 + wm + mt*16 + g + h*8;
                #pragma unroll
                for (int nt = 0; nt < 4; nt++) {
                    int l = l0 + wn + nt*8 + tg*2;
                    *(float2*)&Y[((size_t)b*C_ + co)*L_ + l] =
                        make_float2(acc[mt][nt][h*2+0], acc[mt][nt][h*2+1]);
                }
            }
    } else {
        float (*stage)[132] = reinterpret_cast<float(*)[132]>(dyn);
        #pragma unroll
        for (int wave = 0; wave < 2; wave++) {
            if ((warp_n >> 1) == wave) {
                int lbase = wn - wave*64;
                #pragma unroll
                for (int mt = 0; mt < 4; mt++)
                    #pragma unroll
                    for (int nt = 0; nt < 4; nt++)
                        #pragma unroll
                        for (int h = 0; h < 2; h++) {
                            int ll = lbase + nt*8 + tg*2;
                            int cc = wm + mt*16 + g + h*8;
                            stage[ll][cc]   = acc[mt][nt][h*2+0];
                            stage[ll+1][cc] = acc[mt][nt][h*2+1];
                        }
            }
            __syncthreads();
            #pragma unroll
            for (int i = 0; i < 8; i++) {
                int id = tid + i*256;
                int r = id >> 5, c4 = (id & 31) * 4;
                size_t l = (size_t)l0 + wave*64 + r;
                *(float4*)&Y[((size_t)b*L_ + l)*C_ + m0 + c4] = *(const float4*)&stage[r][c4];
            }
            __syncthreads();
        }
    }
}

// ---------------- LayerNorm: warp per row, float4, in-place ----------------
__global__ void ln_kernel(float* __restrict__ data,
                          const float* __restrict__ gw, const float* __restrict__ bw,
                          int round_out) {
    int lane = threadIdx.x & 31, warp = threadIdx.x >> 5;
    size_t row = (size_t)blockIdx.x * 8 + warp;
    float4* p = (float4*)(data + row * C_);
    float4 a = p[lane], c = p[lane + 32];

    float s = (a.x + a.y) + (a.z + a.w) + (c.x + c.y) + (c.z + c.w);
    #pragma unroll
    for (int o = 16; o; o >>= 1) s += __shfl_xor_sync(0xffffffffu, s, o);
    float mean = s * (1.f / C_);

    float d0 = a.x-mean, d1 = a.y-mean, d2 = a.z-mean, d3 = a.w-mean;
    float d4 = c.x-mean, d5 = c.y-mean, d6 = c.z-mean, d7 = c.w-mean;
    float s2 = (d0*d0 + d1*d1) + (d2*d2 + d3*d3) + (d4*d4 + d5*d5) + (d6*d6 + d7*d7);
    #pragma unroll
    for (int o = 16; o; o >>= 1) s2 += __shfl_xor_sync(0xffffffffu, s2, o);
    float inv = rsqrtf(s2 * (1.f / C_) + 1e-6f);

    const float4* g4 = (const float4*)gw;
    const float4* b4 = (const float4*)bw;
    float4 ga = g4[lane], gc = g4[lane + 32], ba = b4[lane], bc = b4[lane + 32];

    float4 ra = make_float4(d0*inv*ga.x + ba.x, d1*inv*ga.y + ba.y,
                            d2*inv*ga.z + ba.z, d3*inv*ga.w + ba.w);
    float4 rc = make_float4(d4*inv*gc.x + bc.x, d5*inv*gc.y + bc.y,
                            d6*inv*gc.z + bc.z, d7*inv*gc.w + bc.w);
    if (round_out) {
        ra = make_float4(__uint_as_float(f2tf(ra.x)), __uint_as_float(f2tf(ra.y)),
                         __uint_as_float(f2tf(ra.z)), __uint_as_float(f2tf(ra.w)));
        rc = make_float4(__uint_as_float(f2tf(rc.x)), __uint_as_float(f2tf(rc.y)),
                         __uint_as_float(f2tf(rc.z)), __uint_as_float(f2tf(rc.w)));
    }
    p[lane] = ra; p[lane + 32] = rc;
}

// ------- final: out[b,c,l] = relu(xp[b,l,c]*fw[b,l,c] + x[b,c,l]) ----------
__global__ void final_kernel(const float* __restrict__ xp, const float* __restrict__ fw,
                             const float* __restrict__ x, float* __restrict__ out) {
    __shared__ float tile[32][33];
    int b  = blockIdx.z;
    int c0 = blockIdx.x * 32;
    int l0 = blockIdx.y * 32;
    int tx = threadIdx.x, ty = threadIdx.y;   // 32 x 8
    #pragma unroll
    for (int i = 0; i < 32; i += 8) {
        int l = l0 + ty + i;
        size_t idx = ((size_t)b*L_ + l)*C_ + c0 + tx;
        tile[ty+i][tx] = xp[idx] * fw[idx];
    }
    __syncthreads();
    #pragma unroll
    for (int i = 0; i < 32; i += 8) {
        int c = c0 + ty + i;
        int l = l0 + tx;
        size_t idx = ((size_t)b*C_ + c)*L_ + l;
        out[idx] = fmaxf(tile[tx][ty+i] + x[idx], 0.f);
    }
}

// ---------------------------------------------------------------------------
extern "C" void kernel_launch(void* const* d_in, const int* in_sizes, int n_in,
                              void* d_out, int out_size) {
    const float* x       = (const float*)d_in[0];
    const float* conv1_w = (const float*)d_in[1];
    const float* bn1_g   = (const float*)d_in[2];
    const float* bn1_b   = (const float*)d_in[3];
    const float* bn1_m   = (const float*)d_in[4];
    const float* bn1_v   = (const float*)d_in[5];
    const float* conv2_w = (const float*)d_in[6];
    const float* bn2_g   = (const float*)d_in[7];
    const float* bn2_b   = (const float*)d_in[8];
    const float* bn2_m   = (const float*)d_in[9];
    const float* bn2_v   = (const float*)d_in[10];
    const float* fc1_w   = (const float*)d_in[11];
    const float* fc2_w   = (const float*)d_in[12];
    const float* ln_g    = (const float*)d_in[13];
    const float* ln_b    = (const float*)d_in[14];
    float* out = (float*)d_out;

    float *y1, *xp, *t1, *h, *xtf, *dct, *fc1t, *fc2t, *w1p, *w2p;
    cudaGetSymbolAddress((void**)&y1,   g_y1);
    cudaGetSymbolAddress((void**)&xp,   g_xp);
    cudaGetSymbolAddress((void**)&t1,   g_t1);
    cudaGetSymbolAddress((void**)&h,    g_h);
    cudaGetSymbolAddress((void**)&xtf,  g_xtf);
    cudaGetSymbolAddress((void**)&dct,  g_dct);
    cudaGetSymbolAddress((void**)&fc1t, g_fc1t);
    cudaGetSymbolAddress((void**)&fc2t, g_fc2t);
    cudaGetSymbolAddress((void**)&w1p,  g_w1p);
    cudaGetSymbolAddress((void**)&w2p,  g_w2p);

    cudaFuncSetAttribute(sgemm_tc, cudaFuncAttributeMaxDynamicSharedMemorySize, SGEMM_SMEM);
    cudaFuncSetAttribute(conv_tc,  cudaFuncAttributeMaxDynamicSharedMemorySize, CONV_SMEM);

    // 0. precompute tf32 weights + tf32 copy of x
    precompute_kernel<<<(3*C_*C_ + 255)/256, 256>>>(fc1_w, fc2_w, conv1_w, conv2_w);
    tf32_round_kernel<<<(B_*C_*L_/4 + 255)/256, 256>>>((const float4*)x, (uint4*)xtf);

    // 1. conv1 + bn1 + relu -> y1 [B,C,L] (tf32-rounded)
    {
        dim3 grid(L_/128, C_/128, B_);
        conv_tc<<<grid, 256, CONV_SMEM>>>((const uint32_t*)xtf, (const uint32_t*)w1p,
                                          bn1_g, bn1_b, bn1_m, bn1_v, y1, 1, 0);
    }
    // 2. conv2 + bn2 -> xp [B,L,C] (transposed, tf32-rounded)
    {
        dim3 grid(L_/128, C_/128, B_);
        conv_tc<<<grid, 256, CONV_SMEM>>>((const uint32_t*)y1, (const uint32_t*)w2p,
                                          bn2_g, bn2_b, bn2_m, bn2_v, xp, 0, 1);
    }
    // 3. freq = xp @ Dm^T -> t1
    {
        dim3 grid(C_/128, BL_/128);
        sgemm_tc<<<grid, 256, SGEMM_SMEM>>>((const uint32_t*)xp, (const uint32_t*)dct,
                                            t1, BL_, C_, C_, 0);
    }
    // 4. sd = LN(freq), tf32-rounded out
    ln_kernel<<<BL_/8, 256>>>(t1, ln_g, ln_b, 1);
    // 5. h = relu(sd @ fc1^T), tf32-rounded out
    {
        dim3 grid(H_/128, BL_/128);
        sgemm_tc<<<grid, 256, SGEMM_SMEM>>>((const uint32_t*)t1, (const uint32_t*)fc1t,
                                            h, BL_, H_, C_, 1);
    }
    // 6. fw = sigmoid(h @ fc2^T) -> t1
    {
        dim3 grid(C_/128, BL_/128);
        sgemm_tc<<<grid, 256, SGEMM_SMEM>>>((const uint32_t*)h, (const uint32_t*)fc2t,
                                            t1, BL_, C_, H_, 2);
    }
    // 7. fw = LN(fw)
    ln_kernel<<<BL_/8, 256>>>(t1, ln_g, ln_b, 0);
    // 8. out = relu(transpose(xp * fw) + x)
    {
        dim3 grid(C_/32, L_/32, B_);
        final_kernel<<<grid, dim3(32, 8)>>>(xp, t1, x, out);
    }
}

// round 7
// speedup vs baseline: 4.8769x; 1.0430x over previous
#include <cuda_runtime.h>
#include <math.h>
#include <stdint.h>

#define B_ 32
#define C_ 256
#define L_ 4096
#define H_ (2*C_)
#define BL_ (B_*L_)

// ---------------- scratch (device globals; no allocation allowed) ----------
__device__ float g_y1[(size_t)B_*C_*L_];   // conv1 out [B,C,L], tf32-rounded
__device__ float g_xp[(size_t)B_*L_*C_];   // conv2 out transposed [B,L,C], tf32-rounded
__device__ float g_t1[(size_t)B_*L_*C_];   // freq / sd / fw
__device__ float g_h [(size_t)B_*L_*H_];   // hidden [BL, 2C], tf32-rounded
__device__ float g_xtf[(size_t)B_*C_*L_];  // tf32-rounded copy of x
__device__ float g_dct [C_*C_];            // [k_out][n_in] tf32 (N-major for GEMM)
__device__ float g_fc1r[H_*C_];            // fc1_w tf32 (native [j][c] = N-major)
__device__ float g_fc2r[C_*H_];            // fc2_w tf32 (native [c][j] = N-major)
__device__ float g_w1p[3*C_*C_];           // [k][co][ci] tf32
__device__ float g_w2p[3*C_*C_];           // [k][co][ci] tf32

// ---------------- helpers ---------------------------------------------------
__device__ __forceinline__ uint32_t f2tf(float f) {
    uint32_t u; asm("cvt.rna.tf32.f32 %0, %1;" : "=r"(u) : "f"(f)); return u;
}
__device__ __forceinline__ void mma_tf32(float c[4],
        uint32_t a0, uint32_t a1, uint32_t a2, uint32_t a3,
        uint32_t b0, uint32_t b1) {
    asm volatile(
        "mma.sync.aligned.m16n8k8.row.col.f32.tf32.tf32.f32 "
        "{%0,%1,%2,%3}, {%4,%5,%6,%7}, {%8,%9}, {%0,%1,%2,%3};"
        : "+f"(c[0]), "+f"(c[1]), "+f"(c[2]), "+f"(c[3])
        : "r"(a0), "r"(a1), "r"(a2), "r"(a3), "r"(b0), "r"(b1));
}
__device__ __forceinline__ void ldsm4(uint32_t& r0, uint32_t& r1,
                                      uint32_t& r2, uint32_t& r3, uint32_t addr) {
    asm volatile("ldmatrix.sync.aligned.m8n8.x4.shared.b16 {%0,%1,%2,%3}, [%4];"
                 : "=r"(r0), "=r"(r1), "=r"(r2), "=r"(r3) : "r"(addr));
}
__device__ __forceinline__ uint32_t smem_u32(const void* p) {
    return (uint32_t)__cvta_generic_to_shared(p);
}
__device__ __forceinline__ void cp16(uint32_t dst, const void* src) {
    asm volatile("cp.async.cg.shared.global [%0], [%1], 16;" :: "r"(dst), "l"(src));
}
#define CP_COMMIT() asm volatile("cp.async.commit_group;")
#define CP_WAIT0()  asm volatile("cp.async.wait_group 0;")

// ---------------- precompute: DCT + tf32 weights + conv planes -------------
__global__ void precompute_kernel(const float* __restrict__ fc1_w,
                                  const float* __restrict__ fc2_w,
                                  const float* __restrict__ w1,
                                  const float* __restrict__ w2) {
    int idx = blockIdx.x * blockDim.x + threadIdx.x;
    if (idx < C_*C_) {
        int k = idx / C_, n = idx % C_;   // N-major: row = output col k, col = input n
        double v = 2.0 * cos(M_PI * (double)k * (2.0*n + 1.0) / (2.0 * C_));
        g_dct[idx] = __uint_as_float(f2tf((float)v));
    }
    if (idx < C_*H_) {
        g_fc1r[idx] = __uint_as_float(f2tf(fc1_w[idx]));   // [2C][C] native
        g_fc2r[idx] = __uint_as_float(f2tf(fc2_w[idx]));   // [C][2C] native
    }
    if (idx < 3*C_*C_) {
        int p = idx / (C_*C_);
        int rem = idx % (C_*C_);
        int co = rem / C_, ci = rem % C_;
        g_w1p[idx] = __uint_as_float(f2tf(w1[(size_t)co*3*C_ + ci*3 + p]));
        g_w2p[idx] = __uint_as_float(f2tf(w2[(size_t)co*3*C_ + ci*3 + p]));
    }
}

// ---------------- x -> tf32 copy (one pass) ---------------------------------
__global__ void tf32_round_kernel(const float4* __restrict__ in, uint4* __restrict__ out) {
    size_t i = (size_t)blockIdx.x * blockDim.x + threadIdx.x;
    float4 v = in[i];
    out[i] = make_uint4(f2tf(v.x), f2tf(v.y), f2tf(v.z), f2tf(v.w));
}

// ========== TF32 GEMM, cp.async double-buffered, ldmatrix fragments =========
// C[M,N] = A[M,K] @ B; A row-major [M][K], B N-major [N][K] (both tf32 bits).
#define AS_LD 36
#define SGEMM_SMEM ((2*128*AS_LD + 2*128*AS_LD)*4)   // 73728

__global__ void __launch_bounds__(256, 2)
sgemm_tc(const uint32_t* __restrict__ Atf, const uint32_t* __restrict__ BtfN,
         float* __restrict__ Cout, int M, int N, int K, int epi) {
    extern __shared__ uint32_t dyn[];
    uint32_t (*As)[128][AS_LD] = (uint32_t(*)[128][AS_LD])dyn;
    uint32_t (*Bs)[128][AS_LD] = (uint32_t(*)[128][AS_LD])(dyn + 2*128*AS_LD);

    int tid = threadIdx.x, lane = tid & 31, wid = tid >> 5;
    int wm = (wid & 1) * 64, wn = (wid >> 1) * 32;
    int g = lane >> 2, tg = lane & 3;
    int lr = lane & 7, sel = lane >> 3;
    size_t m0 = (size_t)blockIdx.y * 128, n0 = (size_t)blockIdx.x * 128;

    float acc[4][4][4] = {};
    int nk = K >> 5;

    auto load_tile = [&](int t, int buf) {
        int k0 = t * 32;
        #pragma unroll
        for (int i = 0; i < 4; i++) {
            int id = tid + i*256;
            int r = id >> 3, c4 = (id & 7) * 4;
            cp16(smem_u32(&As[buf][r][c4]), &Atf[(m0 + r)*(size_t)K + k0 + c4]);
        }
        #pragma unroll
        for (int i = 0; i < 4; i++) {
            int id = tid + i*256;
            int r = id >> 3, c4 = (id & 7) * 4;
            cp16(smem_u32(&Bs[buf][r][c4]), &BtfN[(n0 + r)*(size_t)K + k0 + c4]);
        }
    };

    load_tile(0, 0); CP_COMMIT(); CP_WAIT0(); __syncthreads();
    int cur = 0;
    for (int t = 0; t < nk; t++) {
        if (t + 1 < nk) { load_tile(t + 1, cur ^ 1); CP_COMMIT(); }
        #pragma unroll
        for (int ks = 0; ks < 4; ks++) {
            int kb = ks * 8;
            uint32_t af[4][4], bf[4][2];
            #pragma unroll
            for (int mt = 0; mt < 4; mt++) {
                uint32_t a = smem_u32(&As[cur][wm + mt*16 + ((sel & 1) << 3) + lr]
                                              [kb + ((sel >> 1) << 2)]);
                ldsm4(af[mt][0], af[mt][1], af[mt][2], af[mt][3], a);
            }
            #pragma unroll
            for (int q = 0; q < 2; q++) {
                uint32_t a = smem_u32(&Bs[cur][wn + ((q*2 + (sel >> 1)) << 3) + lr]
                                              [kb + ((sel & 1) << 2)]);
                ldsm4(bf[q*2][0], bf[q*2][1], bf[q*2+1][0], bf[q*2+1][1], a);
            }
            #pragma unroll
            for (int mt = 0; mt < 4; mt++)
                #pragma unroll
                for (int nt = 0; nt < 4; nt++)
                    mma_tf32(acc[mt][nt], af[mt][0], af[mt][1], af[mt][2], af[mt][3],
                             bf[nt][0], bf[nt][1]);
        }
        if (t + 1 < nk) CP_WAIT0();
        __syncthreads();
        cur ^= 1;
    }

    #pragma unroll
    for (int mt = 0; mt < 4; mt++)
        #pragma unroll
        for (int nt = 0; nt < 4; nt++)
            #pragma unroll
            for (int h = 0; h < 2; h++) {
                size_t row = m0 + wm + mt*16 + g + h*8;
                size_t col = n0 + wn + nt*8 + tg*2;
                float v0 = acc[mt][nt][h*2+0], v1 = acc[mt][nt][h*2+1];
                if (epi == 1) {
                    v0 = __uint_as_float(f2tf(fmaxf(v0, 0.f)));
                    v1 = __uint_as_float(f2tf(fmaxf(v1, 0.f)));
                } else if (epi == 2) {
                    v0 = 1.f/(1.f+expf(-v0)); v1 = 1.f/(1.f+expf(-v1));
                }
                *(float2*)&Cout[row*N + col] = make_float2(v0, v1);
            }
}

// ====== TF32 conv1d(K=3,pad=1)+BN(+relu), cp.async + ldmatrix A frags =======
#define CAS_LD 20
#define CBS_LD 136
#define CONV_SMEM ((2*3*128*CAS_LD + 2*16*CBS_LD)*4)   // 78848

__global__ void __launch_bounds__(256, 2)
conv_tc(const uint32_t* __restrict__ X, const uint32_t* __restrict__ WpU,
        const float* __restrict__ bng, const float* __restrict__ bnb,
        const float* __restrict__ bnm, const float* __restrict__ bnv,
        float* __restrict__ Y, int do_relu, int transpose_out) {
    extern __shared__ uint32_t dyn[];
    uint32_t (*As3)[3][128][CAS_LD] = (uint32_t(*)[3][128][CAS_LD])dyn;
    uint32_t (*Bs)[16][CBS_LD]      = (uint32_t(*)[16][CBS_LD])(dyn + 2*3*128*CAS_LD);

    int tid = threadIdx.x, lane = tid & 31, wid = tid >> 5;
    int b = blockIdx.z, m0 = blockIdx.y * 128, l0 = blockIdx.x * 128;
    int wm = (wid & 1) * 64;
    int warp_n = wid >> 1;
    int wn = warp_n * 32;
    int g = lane >> 2, tg = lane & 3;
    int lr = lane & 7, sel = lane >> 3;
    const uint32_t* xb = X + (size_t)b * C_ * L_;

    float acc[4][4][4] = {};

    auto load_tile = [&](int ci0, int buf) {
        #pragma unroll
        for (int i = 0; i < 6; i++) {
            int id = tid + i*256;
            int p = id >> 9;
            int rem = id & 511;
            int r = rem >> 2, c4 = (rem & 3) * 4;
            cp16(smem_u32(&As3[buf][p][r][c4]),
                 &WpU[(size_t)p*C_*C_ + (size_t)(m0 + r)*C_ + ci0 + c4]);
        }
        #pragma unroll
        for (int i = 0; i < 3; i++) {
            int id = tid + i*256;
            if (id < 16*34) {
                int r = id / 34, c4m = id % 34;
                int gl = l0 + c4m*4 - 4;
                if (gl >= 0 && gl + 4 <= L_)
                    cp16(smem_u32(&Bs[buf][r][c4m*4]), &xb[(size_t)(ci0 + r)*L_ + gl]);
                else
                    *(uint4*)&Bs[buf][r][c4m*4] = make_uint4(0,0,0,0);
            }
        }
    };

    load_tile(0, 0); CP_COMMIT(); CP_WAIT0(); __syncthreads();
    int cur = 0;
    for (int t = 0; t < C_/16; t++) {
        if (t + 1 < C_/16) { load_tile((t+1)*16, cur ^ 1); CP_COMMIT(); }
        #pragma unroll
        for (int ks = 0; ks < 2; ks++) {
            int kb = ks * 8;
            #pragma unroll
            for (int p = 0; p < 3; p++) {
                uint32_t af[4][4], bf[4][2];
                #pragma unroll
                for (int mt = 0; mt < 4; mt++) {
                    uint32_t a = smem_u32(&As3[cur][p][wm + mt*16 + ((sel & 1) << 3) + lr]
                                                    [kb + ((sel >> 1) << 2)]);
                    ldsm4(af[mt][0], af[mt][1], af[mt][2], af[mt][3], a);
                }
                #pragma unroll
                for (int nt = 0; nt < 4; nt++) {
                    int c = wn + nt*8 + g + 3 + p;
                    bf[nt][0] = Bs[cur][kb+tg][c];
                    bf[nt][1] = Bs[cur][kb+tg+4][c];
                }
                #pragma unroll
                for (int mt = 0; mt < 4; mt++)
                    #pragma unroll
                    for (int nt = 0; nt < 4; nt++)
                        mma_tf32(acc[mt][nt], af[mt][0], af[mt][1], af[mt][2], af[mt][3],
                                 bf[nt][0], bf[nt][1]);
            }
        }
        if (t + 1 < C_/16) CP_WAIT0();
        __syncthreads();
        cur ^= 1;
    }

    // BN (+relu) + tf32-round on fragments
    #pragma unroll
    for (int mt = 0; mt < 4; mt++)
        #pragma unroll
        for (int h = 0; h < 2; h++) {
            int co = m0 + wm + mt*16 + g + h*8;
            float scale = bng[co] * rsqrtf(bnv[co] + 1e-5f);
            float shift = bnb[co] - bnm[co]*scale;
            #pragma unroll
            for (int nt = 0; nt < 4; nt++) {
                float v0 = acc[mt][nt][h*2+0]*scale + shift;
                float v1 = acc[mt][nt][h*2+1]*scale + shift;
                if (do_relu) { v0 = fmaxf(v0, 0.f); v1 = fmaxf(v1, 0.f); }
                acc[mt][nt][h*2+0] = __uint_as_float(f2tf(v0));
                acc[mt][nt][h*2+1] = __uint_as_float(f2tf(v1));
            }
        }

    if (!transpose_out) {
        #pragma unroll
        for (int mt = 0; mt < 4; mt++)
            #pragma unroll
            for (int h = 0; h < 2; h++) {
                int co = m0 + wm + mt*16 + g + h*8;
                #pragma unroll
                for (int nt = 0; nt < 4; nt++) {
                    int l = l0 + wn + nt*8 + tg*2;
                    *(float2*)&Y[((size_t)b*C_ + co)*L_ + l] =
                        make_float2(acc[mt][nt][h*2+0], acc[mt][nt][h*2+1]);
                }
            }
    } else {
        float (*stage)[132] = reinterpret_cast<float(*)[132]>(dyn);
        #pragma unroll
        for (int wave = 0; wave < 2; wave++) {
            if ((warp_n >> 1) == wave) {
                int lbase = wn - wave*64;
                #pragma unroll
                for (int mt = 0; mt < 4; mt++)
                    #pragma unroll
                    for (int nt = 0; nt < 4; nt++)
                        #pragma unroll
                        for (int h = 0; h < 2; h++) {
                            int ll = lbase + nt*8 + tg*2;
                            int cc = wm + mt*16 + g + h*8;
                            stage[ll][cc]   = acc[mt][nt][h*2+0];
                            stage[ll+1][cc] = acc[mt][nt][h*2+1];
                        }
            }
            __syncthreads();
            #pragma unroll
            for (int i = 0; i < 8; i++) {
                int id = tid + i*256;
                int r = id >> 5, c4 = (id & 31) * 4;
                size_t l = (size_t)l0 + wave*64 + r;
                *(float4*)&Y[((size_t)b*L_ + l)*C_ + m0 + c4] = *(const float4*)&stage[r][c4];
            }
            __syncthreads();
        }
    }
}

// ---------------- LayerNorm: warp per row, float4, in-place ----------------
__global__ void ln_kernel(float* __restrict__ data,
                          const float* __restrict__ gw, const float* __restrict__ bw,
                          int round_out) {
    int lane = threadIdx.x & 31, warp = threadIdx.x >> 5;
    size_t row = (size_t)blockIdx.x * 8 + warp;
    float4* p = (float4*)(data + row * C_);
    float4 a = p[lane], c = p[lane + 32];

    float s = (a.x + a.y) + (a.z + a.w) + (c.x + c.y) + (c.z + c.w);
    #pragma unroll
    for (int o = 16; o; o >>= 1) s += __shfl_xor_sync(0xffffffffu, s, o);
    float mean = s * (1.f / C_);

    float d0 = a.x-mean, d1 = a.y-mean, d2 = a.z-mean, d3 = a.w-mean;
    float d4 = c.x-mean, d5 = c.y-mean, d6 = c.z-mean, d7 = c.w-mean;
    float s2 = (d0*d0 + d1*d1) + (d2*d2 + d3*d3) + (d4*d4 + d5*d5) + (d6*d6 + d7*d7);
    #pragma unroll
    for (int o = 16; o; o >>= 1) s2 += __shfl_xor_sync(0xffffffffu, s2, o);
    float inv = rsqrtf(s2 * (1.f / C_) + 1e-6f);

    const float4* g4 = (const float4*)gw;
    const float4* b4 = (const float4*)bw;
    float4 ga = g4[lane], gc = g4[lane + 32], ba = b4[lane], bc = b4[lane + 32];

    float4 ra = make_float4(d0*inv*ga.x + ba.x, d1*inv*ga.y + ba.y,
                            d2*inv*ga.z + ba.z, d3*inv*ga.w + ba.w);
    float4 rc = make_float4(d4*inv*gc.x + bc.x, d5*inv*gc.y + bc.y,
                            d6*inv*gc.z + bc.z, d7*inv*gc.w + bc.w);
    if (round_out) {
        ra = make_float4(__uint_as_float(f2tf(ra.x)), __uint_as_float(f2tf(ra.y)),
                         __uint_as_float(f2tf(ra.z)), __uint_as_float(f2tf(ra.w)));
        rc = make_float4(__uint_as_float(f2tf(rc.x)), __uint_as_float(f2tf(rc.y)),
                         __uint_as_float(f2tf(rc.z)), __uint_as_float(f2tf(rc.w)));
    }
    p[lane] = ra; p[lane + 32] = rc;
}

// ------- final: out[b,c,l] = relu(xp[b,l,c]*fw[b,l,c] + x[b,c,l]) ----------
__global__ void final_kernel(const float* __restrict__ xp, const float* __restrict__ fw,
                             const float* __restrict__ x, float* __restrict__ out) {
    __shared__ float tile[32][33];
    int b  = blockIdx.z;
    int c0 = blockIdx.x * 32;
    int l0 = blockIdx.y * 32;
    int tx = threadIdx.x, ty = threadIdx.y;   // 32 x 8
    #pragma unroll
    for (int i = 0; i < 32; i += 8) {
        int l = l0 + ty + i;
        size_t idx = ((size_t)b*L_ + l)*C_ + c0 + tx;
        tile[ty+i][tx] = xp[idx] * fw[idx];
    }
    __syncthreads();
    #pragma unroll
    for (int i = 0; i < 32; i += 8) {
        int c = c0 + ty + i;
        int l = l0 + tx;
        size_t idx = ((size_t)b*C_ + c)*L_ + l;
        out[idx] = fmaxf(tile[tx][ty+i] + x[idx], 0.f);
    }
}

// ---------------------------------------------------------------------------
extern "C" void kernel_launch(void* const* d_in, const int* in_sizes, int n_in,
                              void* d_out, int out_size) {
    const float* x       = (const float*)d_in[0];
    const float* conv1_w = (const float*)d_in[1];
    const float* bn1_g   = (const float*)d_in[2];
    const float* bn1_b   = (const float*)d_in[3];
    const float* bn1_m   = (const float*)d_in[4];
    const float* bn1_v   = (const float*)d_in[5];
    const float* conv2_w = (const float*)d_in[6];
    const float* bn2_g   = (const float*)d_in[7];
    const float* bn2_b   = (const float*)d_in[8];
    const float* bn2_m   = (const float*)d_in[9];
    const float* bn2_v   = (const float*)d_in[10];
    const float* fc1_w   = (const float*)d_in[11];
    const float* fc2_w   = (const float*)d_in[12];
    const float* ln_g    = (const float*)d_in[13];
    const float* ln_b    = (const float*)d_in[14];
    float* out = (float*)d_out;

    float *y1, *xp, *t1, *h, *xtf, *dct, *fc1r, *fc2r, *w1p, *w2p;
    cudaGetSymbolAddress((void**)&y1,   g_y1);
    cudaGetSymbolAddress((void**)&xp,   g_xp);
    cudaGetSymbolAddress((void**)&t1,   g_t1);
    cudaGetSymbolAddress((void**)&h,    g_h);
    cudaGetSymbolAddress((void**)&xtf,  g_xtf);
    cudaGetSymbolAddress((void**)&dct,  g_dct);
    cudaGetSymbolAddress((void**)&fc1r, g_fc1r);
    cudaGetSymbolAddress((void**)&fc2r, g_fc2r);
    cudaGetSymbolAddress((void**)&w1p,  g_w1p);
    cudaGetSymbolAddress((void**)&w2p,  g_w2p);

    cudaFuncSetAttribute(sgemm_tc, cudaFuncAttributeMaxDynamicSharedMemorySize, SGEMM_SMEM);
    cudaFuncSetAttribute(conv_tc,  cudaFuncAttributeMaxDynamicSharedMemorySize, CONV_SMEM);

    // 0. precompute tf32 weights + tf32 copy of x
    precompute_kernel<<<(3*C_*C_ + 255)/256, 256>>>(fc1_w, fc2_w, conv1_w, conv2_w);
    tf32_round_kernel<<<(B_*C_*L_/4 + 255)/256, 256>>>((const float4*)x, (uint4*)xtf);

    // 1. conv1 + bn1 + relu -> y1 [B,C,L]
    {
        dim3 grid(L_/128, C_/128, B_);
        conv_tc<<<grid, 256, CONV_SMEM>>>((const uint32_t*)xtf, (const uint32_t*)w1p,
                                          bn1_g, bn1_b, bn1_m, bn1_v, y1, 1, 0);
    }
    // 2. conv2 + bn2 -> xp [B,L,C] (transposed)
    {
        dim3 grid(L_/128, C_/128, B_);
        conv_tc<<<grid, 256, CONV_SMEM>>>((const uint32_t*)y1, (const uint32_t*)w2p,
                                          bn2_g, bn2_b, bn2_m, bn2_v, xp, 0, 1);
    }
    // 3. freq = xp @ Dm^T -> t1   (B = g_dct, N-major [k][n])
    {
        dim3 grid(C_/128, BL_/128);
        sgemm_tc<<<grid, 256, SGEMM_SMEM>>>((const uint32_t*)xp, (const uint32_t*)dct,
                                            t1, BL_, C_, C_, 0);
    }
    // 4. sd = LN(freq), tf32-rounded out
    ln_kernel<<<BL_/8, 256>>>(t1, ln_g, ln_b, 1);
    // 5. h = relu(sd @ fc1^T)   (B = fc1_w native [j][c] = N-major)
    {
        dim3 grid(H_/128, BL_/128);
        sgemm_tc<<<grid, 256, SGEMM_SMEM>>>((const uint32_t*)t1, (const uint32_t*)fc1r,
                                            h, BL_, H_, C_, 1);
    }
    // 6. fw = sigmoid(h @ fc2^T)  (B = fc2_w native [c][j] = N-major)
    {
        dim3 grid(C_/128, BL_/128);
        sgemm_tc<<<grid, 256, SGEMM_SMEM>>>((const uint32_t*)h, (const uint32_t*)fc2r,
                                            t1, BL_, C_, H_, 2);
    }
    // 7. fw = LN(fw)
    ln_kernel<<<BL_/8, 256>>>(t1, ln_g, ln_b, 0);
    // 8. out = relu(transpose(xp * fw) + x)
    {
        dim3 grid(C_/32, L_/32, B_);
        final_kernel<<<grid, dim3(32, 8)>>>(xp, t1, x, out);
    }
}

// round 9
// speedup vs baseline: 8.1951x; 1.6804x over previous
#include <cuda_runtime.h>
#include <cuda_fp16.h>
#include <math.h>
#include <stdint.h>

#define B_ 32
#define C_ 256
#define L_ 4096
#define H_ (2*C_)
#define BL_ (B_*L_)

// ---------------- scratch (device globals; no allocation allowed) ----------
__device__ uint16_t g_xt[(size_t)B_*L_*C_];   // x transposed [B,L,C], fp16
__device__ uint16_t g_y1[(size_t)B_*L_*C_];   // conv1 out [B,L,C], fp16
__device__ uint16_t g_xp[(size_t)B_*L_*C_];   // conv2 out [B,L,C], fp16
__device__ uint16_t g_t1[(size_t)B_*L_*C_];   // freq / sd / fw, fp16
__device__ uint16_t g_h [(size_t)B_*L_*H_];   // hidden [BL,2C], fp16
__device__ uint16_t g_dct [C_*C_];            // [N=256][K=256] fp16
__device__ uint16_t g_fc1r[H_*C_];            // [N=2C][K=C] fp16 (native)
__device__ uint16_t g_fc2r[C_*H_];            // [N=C][K=2C] fp16 (native)
__device__ uint16_t g_w1r[C_*3*C_];           // [co][k*C+ci] fp16
__device__ uint16_t g_w2r[C_*3*C_];           // [co][k*C+ci] fp16
__device__ float g_bn1s[C_], g_bn1t[C_], g_bn2s[C_], g_bn2t[C_];

// ---------------- helpers ---------------------------------------------------
__device__ __forceinline__ uint32_t smem_u32(const void* p) {
    return (uint32_t)__cvta_generic_to_shared(p);
}
__device__ __forceinline__ void cp16p(uint32_t dst, const void* src, uint32_t sz) {
    asm volatile("cp.async.cg.shared.global [%0], [%1], 16, %2;"
                 :: "r"(dst), "l"(src), "r"(sz));
}
#define CP_COMMIT() asm volatile("cp.async.commit_group;")
#define CP_WAIT0()  asm volatile("cp.async.wait_group 0;" ::: "memory")
#define CP_WAIT1()  asm volatile("cp.async.wait_group 1;" ::: "memory")

__device__ __forceinline__ void mma_f16(float c[4],
        uint32_t a0, uint32_t a1, uint32_t a2, uint32_t a3,
        uint32_t b0, uint32_t b1) {
    asm volatile(
        "mma.sync.aligned.m16n8k16.row.col.f32.f16.f16.f32 "
        "{%0,%1,%2,%3}, {%4,%5,%6,%7}, {%8,%9}, {%0,%1,%2,%3};"
        : "+f"(c[0]), "+f"(c[1]), "+f"(c[2]), "+f"(c[3])
        : "r"(a0), "r"(a1), "r"(a2), "r"(a3), "r"(b0), "r"(b1));
}
__device__ __forceinline__ void ldsm4(uint32_t& r0, uint32_t& r1,
                                      uint32_t& r2, uint32_t& r3, uint32_t addr) {
    asm volatile("ldmatrix.sync.aligned.m8n8.x4.shared.b16 {%0,%1,%2,%3}, [%4];"
                 : "=r"(r0), "=r"(r1), "=r"(r2), "=r"(r3) : "r"(addr));
}

// ---------------- precompute: all weights (fp16) + BN affines ---------------
__global__ void precompute_kernel(const float* __restrict__ fc1_w,
                                  const float* __restrict__ fc2_w,
                                  const float* __restrict__ w1,
                                  const float* __restrict__ w2,
                                  const float* __restrict__ bn1_g, const float* __restrict__ bn1_b,
                                  const float* __restrict__ bn1_m, const float* __restrict__ bn1_v,
                                  const float* __restrict__ bn2_g, const float* __restrict__ bn2_b,
                                  const float* __restrict__ bn2_m, const float* __restrict__ bn2_v) {
    int idx = blockIdx.x * blockDim.x + threadIdx.x;
    if (idx < C_) {
        float s1 = bn1_g[idx] * rsqrtf(bn1_v[idx] + 1e-5f);
        g_bn1s[idx] = s1; g_bn1t[idx] = bn1_b[idx] - bn1_m[idx]*s1;
        float s2 = bn2_g[idx] * rsqrtf(bn2_v[idx] + 1e-5f);
        g_bn2s[idx] = s2; g_bn2t[idx] = bn2_b[idx] - bn2_m[idx]*s2;
    }
    if (idx < C_*C_) {
        int k = idx / C_, n = idx % C_;   // row = DCT output index, col = input
        double v = 2.0 * cos(M_PI * (double)k * (2.0*n + 1.0) / (2.0 * C_));
        g_dct[idx] = __half_as_ushort(__float2half_rn((float)v));
    }
    if (idx < C_*H_) {
        g_fc1r[idx] = __half_as_ushort(__float2half_rn(fc1_w[idx]));
        g_fc2r[idx] = __half_as_ushort(__float2half_rn(fc2_w[idx]));
    }
    if (idx < 3*C_*C_) {
        int co = idx / (3*C_);
        int rem = idx % (3*C_);
        int k = rem / C_, ci = rem % C_;
        g_w1r[idx] = __half_as_ushort(__float2half_rn(w1[(size_t)co*3*C_ + ci*3 + k]));
        g_w2r[idx] = __half_as_ushort(__float2half_rn(w2[(size_t)co*3*C_ + ci*3 + k]));
    }
}

// ---------------- transpose + round: xt[b][l][c] = fp16(x[b][c][l]) --------
__global__ void transpose_round_kernel(const float* __restrict__ x, __half* __restrict__ xt) {
    __shared__ float tile[32][33];
    int b = blockIdx.z, c0 = blockIdx.x*32, l0 = blockIdx.y*32;
    int tx = threadIdx.x, ty = threadIdx.y;   // 32 x 8
    #pragma unroll
    for (int i = 0; i < 32; i += 8)
        tile[ty+i][tx] = x[((size_t)b*C_ + c0+ty+i)*L_ + l0 + tx];
    __syncthreads();
    #pragma unroll
    for (int i = 0; i < 32; i += 8)
        xt[((size_t)b*L_ + l0+ty+i)*C_ + c0 + tx] = __float2half_rn(tile[tx][ty+i]);
}

// ========== unified fp16 tensor-core GEMM: D[m,n] = sum_K A' B[n,K] =========
// A: flat [M,K] fp16, or conv mode ([B,L,C] with K=(tap,ci), row l+tap-1).
// B: [N,K] row-major fp16. CTA 128x128, K=64/stage, 2-stage cp.async.
// epi: 0 none, 1 relu, 2 sigmoid, 3 BN(col), 4 BN(col)+relu.  D: fp16 [M,N].
#define HLD 72                       // halfs per smem row (144 B)
#define TILEB (128*144)              // 18432 B per operand per stage
#define GH_SMEM (4*TILEB)            // 73728

__global__ void __launch_bounds__(256, 2)
gemmh(const __half* __restrict__ A, const __half* __restrict__ Bw,
      __half* __restrict__ D, int N, int K, int conv_mode,
      const float* __restrict__ e1, const float* __restrict__ e2, int epi) {
    extern __shared__ unsigned char sm[];
    const uint32_t sbase = smem_u32(sm);

    int tid = threadIdx.x, lane = tid & 31, wid = tid >> 5;
    int wm = (wid & 1) * 64, wn = (wid >> 1) * 32;
    int g = lane >> 2, tg = lane & 3;
    int lr = lane & 7, sel = lane >> 3;
    size_t n0 = (size_t)blockIdx.x * 128;
    size_t m0 = (size_t)blockIdx.y * 128;
    int bidx = (int)(m0 >> 12);          // conv: batch (L_=4096)
    int l0   = (int)(m0 & (L_ - 1));     // conv: l base

    float acc[4][4][4] = {};
    int ntls = K >> 6;

    auto load_tile = [&](int t, int buf) {
        uint32_t ab = sbase + buf * TILEB;
        uint32_t bb = sbase + 2 * TILEB + buf * TILEB;
        #pragma unroll
        for (int i = 0; i < 4; i++) {
            int ch = tid + i * 256;          // 0..1023
            int r = ch >> 3, c16 = ch & 7;   // row, 16B chunk (8 halfs)
            uint32_t doff = r * 144 + c16 * 16;
            if (conv_mode) {
                int tap = t >> 2;                       // 4 tiles of 64 per tap
                int ci0 = (t & 3) * 64 + c16 * 8;
                int sl = l0 + r + tap - 1;
                uint32_t sz = ((unsigned)sl < (unsigned)L_) ? 16u : 0u;
                int slc = sl < 0 ? 0 : (sl >= L_ ? L_ - 1 : sl);
                cp16p(ab + doff, &A[((size_t)bidx * L_ + slc) * C_ + ci0], sz);
            } else {
                cp16p(ab + doff, &A[(m0 + r) * (size_t)K + t * 64 + c16 * 8], 16);
            }
            cp16p(bb + doff, &Bw[(n0 + r) * (size_t)K + t * 64 + c16 * 8], 16);
        }
    };

    load_tile(0, 0); CP_COMMIT();
    if (ntls > 1) { load_tile(1, 1); CP_COMMIT(); }

    for (int t = 0; t < ntls; t++) {
        if (t + 1 < ntls) CP_WAIT1(); else CP_WAIT0();
        __syncthreads();
        int buf = t & 1;
        uint32_t ab = sbase + buf * TILEB;
        uint32_t bb = sbase + 2 * TILEB + buf * TILEB;
        #pragma unroll
        for (int ks = 0; ks < 4; ks++) {
            int kb = ks * 16;                 // halfs
            uint32_t af[4][4], bf[4][2];
            #pragma unroll
            for (int mt = 0; mt < 4; mt++) {
                uint32_t a = ab + (uint32_t)(wm + mt*16 + (sel & 1)*8 + lr) * 144
                                + (uint32_t)(kb + (sel >> 1)*8) * 2;
                ldsm4(af[mt][0], af[mt][1], af[mt][2], af[mt][3], a);
            }
            #pragma unroll
            for (int q = 0; q < 2; q++) {
                uint32_t a = bb + (uint32_t)(wn + q*16 + (sel >> 1)*8 + lr) * 144
                                + (uint32_t)(kb + (sel & 1)*8) * 2;
                ldsm4(bf[q*2][0], bf[q*2][1], bf[q*2+1][0], bf[q*2+1][1], a);
            }
            #pragma unroll
            for (int mt = 0; mt < 4; mt++)
                #pragma unroll
                for (int nt = 0; nt < 4; nt++)
                    mma_f16(acc[mt][nt], af[mt][0], af[mt][1], af[mt][2], af[mt][3],
                            bf[nt][0], bf[nt][1]);
        }
        __syncthreads();
        if (t + 2 < ntls) { load_tile(t + 2, buf); CP_COMMIT(); }
    }

    // ---- epilogue ----------------------------------------------------------
    #pragma unroll
    for (int mt = 0; mt < 4; mt++)
        #pragma unroll
        for (int nt = 0; nt < 4; nt++)
            #pragma unroll
            for (int h = 0; h < 2; h++) {
                size_t row = m0 + wm + mt*16 + g + h*8;
                int col = (int)n0 + wn + nt*8 + tg*2;
                float v0 = acc[mt][nt][h*2+0], v1 = acc[mt][nt][h*2+1];
                if (epi == 1) { v0 = fmaxf(v0, 0.f); v1 = fmaxf(v1, 0.f); }
                else if (epi == 2) { v0 = 1.f/(1.f+expf(-v0)); v1 = 1.f/(1.f+expf(-v1)); }
                else if (epi >= 3) {
                    v0 = v0 * e1[col]   + e2[col];
                    v1 = v1 * e1[col+1] + e2[col+1];
                    if (epi == 4) { v0 = fmaxf(v0, 0.f); v1 = fmaxf(v1, 0.f); }
                }
                *(__half2*)&D[row * (size_t)N + col] = __floats2half2_rn(v0, v1);
            }
}

// ---------------- LayerNorm (fp16 data): warp per row, in-place ------------
__global__ void ln_kernel(__half* __restrict__ data,
                          const float* __restrict__ gw, const float* __restrict__ bw) {
    int lane = threadIdx.x & 31, warp = threadIdx.x >> 5;
    size_t row = (size_t)blockIdx.x * 8 + warp;
    uint4* p = (uint4*)(data + row * C_);
    uint4 raw = p[lane];
    __half2 hp[4];
    *(uint4*)hp = raw;
    float v[8];
    #pragma unroll
    for (int q = 0; q < 4; q++) {
        float2 f = __half22float2(hp[q]);
        v[q*2] = f.x; v[q*2+1] = f.y;
    }
    float s = 0.f;
    #pragma unroll
    for (int j = 0; j < 8; j++) s += v[j];
    #pragma unroll
    for (int o = 16; o; o >>= 1) s += __shfl_xor_sync(0xffffffffu, s, o);
    float mean = s * (1.f / C_);
    float s2 = 0.f;
    #pragma unroll
    for (int j = 0; j < 8; j++) { v[j] -= mean; s2 += v[j]*v[j]; }
    #pragma unroll
    for (int o = 16; o; o >>= 1) s2 += __shfl_xor_sync(0xffffffffu, s2, o);
    float inv = rsqrtf(s2 * (1.f / C_) + 1e-6f);

    const float4* g4 = (const float4*)gw;
    const float4* b4 = (const float4*)bw;
    float4 ga = g4[lane*2], gb = g4[lane*2+1], ba = b4[lane*2], bb = b4[lane*2+1];
    float gv[8] = {ga.x, ga.y, ga.z, ga.w, gb.x, gb.y, gb.z, gb.w};
    float bv[8] = {ba.x, ba.y, ba.z, ba.w, bb.x, bb.y, bb.z, bb.w};
    #pragma unroll
    for (int q = 0; q < 4; q++)
        hp[q] = __floats2half2_rn(v[q*2]*inv*gv[q*2] + bv[q*2],
                                  v[q*2+1]*inv*gv[q*2+1] + bv[q*2+1]);
    p[lane] = *(uint4*)hp;
}

// ------- final: out[b,c,l] = relu(xp[b,l,c]*fw[b,l,c] + x[b,c,l]) ----------
__global__ void final_kernel(const __half* __restrict__ xp, const __half* __restrict__ fw,
                             const float* __restrict__ x, float* __restrict__ out) {
    __shared__ float tile[32][33];
    int b  = blockIdx.z;
    int c0 = blockIdx.x * 32;
    int l0 = blockIdx.y * 32;
    int tx = threadIdx.x, ty = threadIdx.y;   // 32 x 8
    #pragma unroll
    for (int i = 0; i < 32; i += 8) {
        int l = l0 + ty + i;
        size_t idx = ((size_t)b*L_ + l)*C_ + c0 + tx;
        tile[ty+i][tx] = __half2float(xp[idx]) * __half2float(fw[idx]);
    }
    __syncthreads();
    #pragma unroll
    for (int i = 0; i < 32; i += 8) {
        int c = c0 + ty + i;
        int l = l0 + tx;
        size_t idx = ((size_t)b*C_ + c)*L_ + l;
        out[idx] = fmaxf(tile[tx][ty+i] + x[idx], 0.f);
    }
}

// ---------------------------------------------------------------------------
extern "C" void kernel_launch(void* const* d_in, const int* in_sizes, int n_in,
                              void* d_out, int out_size) {
    const float* x       = (const float*)d_in[0];
    const float* conv1_w = (const float*)d_in[1];
    const float* bn1_g   = (const float*)d_in[2];
    const float* bn1_b   = (const float*)d_in[3];
    const float* bn1_m   = (const float*)d_in[4];
    const float* bn1_v   = (const float*)d_in[5];
    const float* conv2_w = (const float*)d_in[6];
    const float* bn2_g   = (const float*)d_in[7];
    const float* bn2_b   = (const float*)d_in[8];
    const float* bn2_m   = (const float*)d_in[9];
    const float* bn2_v   = (const float*)d_in[10];
    const float* fc1_w   = (const float*)d_in[11];
    const float* fc2_w   = (const float*)d_in[12];
    const float* ln_g    = (const float*)d_in[13];
    const float* ln_b    = (const float*)d_in[14];
    float* out = (float*)d_out;

    void *xt, *y1, *xp, *t1, *h, *dct, *fc1r, *fc2r, *w1r, *w2r;
    void *bn1s, *bn1t, *bn2s, *bn2t;
    cudaGetSymbolAddress(&xt,   g_xt);
    cudaGetSymbolAddress(&y1,   g_y1);
    cudaGetSymbolAddress(&xp,   g_xp);
    cudaGetSymbolAddress(&t1,   g_t1);
    cudaGetSymbolAddress(&h,    g_h);
    cudaGetSymbolAddress(&dct,  g_dct);
    cudaGetSymbolAddress(&fc1r, g_fc1r);
    cudaGetSymbolAddress(&fc2r, g_fc2r);
    cudaGetSymbolAddress(&w1r,  g_w1r);
    cudaGetSymbolAddress(&w2r,  g_w2r);
    cudaGetSymbolAddress(&bn1s, g_bn1s);
    cudaGetSymbolAddress(&bn1t, g_bn1t);
    cudaGetSymbolAddress(&bn2s, g_bn2s);
    cudaGetSymbolAddress(&bn2t, g_bn2t);

    cudaFuncSetAttribute(gemmh, cudaFuncAttributeMaxDynamicSharedMemorySize, GH_SMEM);

    // 0. precompute fp16 weights + transpose/round x
    precompute_kernel<<<(3*C_*C_ + 255)/256, 256>>>(
        fc1_w, fc2_w, conv1_w, conv2_w,
        bn1_g, bn1_b, bn1_m, bn1_v, bn2_g, bn2_b, bn2_m, bn2_v);
    {
        dim3 grid(C_/32, L_/32, B_);
        transpose_round_kernel<<<grid, dim3(32, 8)>>>(x, (__half*)xt);
    }

    // 1. conv1+bn1+relu -> y1 [B,L,C]
    gemmh<<<dim3(C_/128, BL_/128), 256, GH_SMEM>>>(
        (const __half*)xt, (const __half*)w1r, (__half*)y1, C_, 3*C_, 1,
        (const float*)bn1s, (const float*)bn1t, 4);
    // 2. conv2+bn2 -> xp [B,L,C]
    gemmh<<<dim3(C_/128, BL_/128), 256, GH_SMEM>>>(
        (const __half*)y1, (const __half*)w2r, (__half*)xp, C_, 3*C_, 1,
        (const float*)bn2s, (const float*)bn2t, 3);
    // 3. freq = xp @ Dm^T -> t1
    gemmh<<<dim3(C_/128, BL_/128), 256, GH_SMEM>>>(
        (const __half*)xp, (const __half*)dct, (__half*)t1, C_, C_, 0,
        nullptr, nullptr, 0);
    // 4. sd = LN(freq)
    ln_kernel<<<BL_/8, 256>>>((__half*)t1, ln_g, ln_b);
    // 5. h = relu(sd @ fc1^T)
    gemmh<<<dim3(H_/128, BL_/128), 256, GH_SMEM>>>(
        (const __half*)t1, (const __half*)fc1r, (__half*)h, H_, C_, 0,
        nullptr, nullptr, 1);
    // 6. fw = sigmoid(h @ fc2^T) -> t1
    gemmh<<<dim3(C_/128, BL_/128), 256, GH_SMEM>>>(
        (const __half*)h, (const __half*)fc2r, (__half*)t1, C_, H_, 0,
        nullptr, nullptr, 2);
    // 7. fw = LN(fw)
    ln_kernel<<<BL_/8, 256>>>((__half*)t1, ln_g, ln_b);
    // 8. out = relu(transpose(xp * fw) + x)
    {
        dim3 grid(C_/32, L_/32, B_);
        final_kernel<<<grid, dim3(32, 8)>>>((const __half*)xp, (const __half*)t1, x, out);
    }
}

// round 10
// speedup vs baseline: 8.7182x; 1.0638x over previous
#include <cuda_runtime.h>
#include <cuda_fp16.h>
#include <math.h>
#include <stdint.h>

#define B_ 32
#define C_ 256
#define L_ 4096
#define H_ (2*C_)
#define BL_ (B_*L_)

// ---------------- scratch (device globals; no allocation allowed) ----------
__device__ uint16_t g_xt[(size_t)B_*L_*C_];   // x transposed [B,L,C], fp16
__device__ uint16_t g_y1[(size_t)B_*L_*C_];   // conv1 out [B,L,C], fp16
__device__ uint16_t g_xp[(size_t)B_*L_*C_];   // conv2 out [B,L,C], fp16
__device__ uint16_t g_t1[(size_t)B_*L_*C_];   // freq / sd / fw, fp16
__device__ uint16_t g_h [(size_t)B_*L_*H_];   // hidden [BL,2C], fp16
__device__ uint16_t g_dct [C_*C_];            // [N=256][K=256] fp16
__device__ uint16_t g_fc1r[H_*C_];            // [N=2C][K=C] fp16 (native)
__device__ uint16_t g_fc2r[C_*H_];            // [N=C][K=2C] fp16 (native)
__device__ uint16_t g_w1r[C_*3*C_];           // [co][k*C+ci] fp16
__device__ uint16_t g_w2r[C_*3*C_];           // [co][k*C+ci] fp16
__device__ float g_bn1s[C_], g_bn1t[C_], g_bn2s[C_], g_bn2t[C_];

// ---------------- helpers ---------------------------------------------------
__device__ __forceinline__ uint32_t smem_u32(const void* p) {
    return (uint32_t)__cvta_generic_to_shared(p);
}
__device__ __forceinline__ void cp16p(uint32_t dst, const void* src, uint32_t sz) {
    asm volatile("cp.async.cg.shared.global [%0], [%1], 16, %2;"
                 :: "r"(dst), "l"(src), "r"(sz));
}
#define CP_COMMIT() asm volatile("cp.async.commit_group;")
#define CP_WAIT0()  asm volatile("cp.async.wait_group 0;" ::: "memory")
#define CP_WAIT1()  asm volatile("cp.async.wait_group 1;" ::: "memory")

__device__ __forceinline__ void mma_f16(float c[4],
        uint32_t a0, uint32_t a1, uint32_t a2, uint32_t a3,
        uint32_t b0, uint32_t b1) {
    asm volatile(
        "mma.sync.aligned.m16n8k16.row.col.f32.f16.f16.f32 "
        "{%0,%1,%2,%3}, {%4,%5,%6,%7}, {%8,%9}, {%0,%1,%2,%3};"
        : "+f"(c[0]), "+f"(c[1]), "+f"(c[2]), "+f"(c[3])
        : "r"(a0), "r"(a1), "r"(a2), "r"(a3), "r"(b0), "r"(b1));
}
__device__ __forceinline__ void ldsm4(uint32_t& r0, uint32_t& r1,
                                      uint32_t& r2, uint32_t& r3, uint32_t addr) {
    asm volatile("ldmatrix.sync.aligned.m8n8.x4.shared.b16 {%0,%1,%2,%3}, [%4];"
                 : "=r"(r0), "=r"(r1), "=r"(r2), "=r"(r3) : "r"(addr));
}

// ---------------- precompute: all weights (fp16) + BN affines ---------------
__global__ void precompute_kernel(const float* __restrict__ fc1_w,
                                  const float* __restrict__ fc2_w,
                                  const float* __restrict__ w1,
                                  const float* __restrict__ w2,
                                  const float* __restrict__ bn1_g, const float* __restrict__ bn1_b,
                                  const float* __restrict__ bn1_m, const float* __restrict__ bn1_v,
                                  const float* __restrict__ bn2_g, const float* __restrict__ bn2_b,
                                  const float* __restrict__ bn2_m, const float* __restrict__ bn2_v) {
    int idx = blockIdx.x * blockDim.x + threadIdx.x;
    if (idx < C_) {
        float s1 = bn1_g[idx] * rsqrtf(bn1_v[idx] + 1e-5f);
        g_bn1s[idx] = s1; g_bn1t[idx] = bn1_b[idx] - bn1_m[idx]*s1;
        float s2 = bn2_g[idx] * rsqrtf(bn2_v[idx] + 1e-5f);
        g_bn2s[idx] = s2; g_bn2t[idx] = bn2_b[idx] - bn2_m[idx]*s2;
    }
    if (idx < C_*C_) {
        int k = idx / C_, n = idx % C_;
        double v = 2.0 * cos(M_PI * (double)k * (2.0*n + 1.0) / (2.0 * C_));
        g_dct[idx] = __half_as_ushort(__float2half_rn((float)v));
    }
    if (idx < C_*H_) {
        g_fc1r[idx] = __half_as_ushort(__float2half_rn(fc1_w[idx]));
        g_fc2r[idx] = __half_as_ushort(__float2half_rn(fc2_w[idx]));
    }
    if (idx < 3*C_*C_) {
        int co = idx / (3*C_);
        int rem = idx % (3*C_);
        int k = rem / C_, ci = rem % C_;
        g_w1r[idx] = __half_as_ushort(__float2half_rn(w1[(size_t)co*3*C_ + ci*3 + k]));
        g_w2r[idx] = __half_as_ushort(__float2half_rn(w2[(size_t)co*3*C_ + ci*3 + k]));
    }
}

// ---------------- transpose + round: xt[b][l][c] = fp16(x[b][c][l]) --------
__global__ void transpose_round_kernel(const float* __restrict__ x, __half* __restrict__ xt) {
    __shared__ float tile[32][33];
    int b = blockIdx.z, c0 = blockIdx.x*32, l0 = blockIdx.y*32;
    int tx = threadIdx.x, ty = threadIdx.y;   // 32 x 8
    #pragma unroll
    for (int i = 0; i < 32; i += 8)
        tile[ty+i][tx] = x[((size_t)b*C_ + c0+ty+i)*L_ + l0 + tx];
    __syncthreads();
    #pragma unroll
    for (int i = 0; i < 32; i += 8)
        xt[((size_t)b*L_ + l0+ty+i)*C_ + c0 + tx] = __float2half_rn(tile[tx][ty+i]);
}

// ========== unified fp16 tensor-core GEMM, 3-stage, 1 sync/ktile ===========
// A: flat [M,K] fp16, or conv mode ([B,L,C] with K=(tap,ci), row l+tap-1).
// B: [N,K] row-major fp16. CTA 128x128, K=64/stage.
// epi: 0 none, 1 relu, 2 sigmoid, 3 BN(col), 4 BN(col)+relu.  D: fp16 [M,N].
#define TILEB (128*144)              // 18432 B per operand per stage
#define GH_SMEM (6*TILEB)            // 110592 (3 stages x A,B)

__global__ void __launch_bounds__(256, 2)
gemmh(const __half* __restrict__ A, const __half* __restrict__ Bw,
      __half* __restrict__ D, int N, int K, int conv_mode,
      const float* __restrict__ e1, const float* __restrict__ e2, int epi) {
    extern __shared__ unsigned char sm[];
    const uint32_t sbase = smem_u32(sm);

    int tid = threadIdx.x, lane = tid & 31, wid = tid >> 5;
    int wm = (wid & 1) * 64, wn = (wid >> 1) * 32;
    int g = lane >> 2, tg = lane & 3;
    int lr = lane & 7, sel = lane >> 3;
    size_t n0 = (size_t)blockIdx.x * 128;
    size_t m0 = (size_t)blockIdx.y * 128;
    int bidx = (int)(m0 >> 12);          // conv: batch (L_=4096)
    int l0   = (int)(m0 & (L_ - 1));     // conv: l base

    float acc[4][4][4] = {};
    int ntls = K >> 6;

    // per-thread loader constants (hoisted)
    int ldr_r = 0, ldr_c16 = 0;          // set in loop over 4 chunks below

    auto load_tile = [&](int t, int slot) {
        uint32_t ab = sbase + (uint32_t)slot * TILEB;
        uint32_t bb = sbase + 3u * TILEB + (uint32_t)slot * TILEB;
        #pragma unroll
        for (int i = 0; i < 4; i++) {
            int ch = tid + i * 256;          // 0..1023
            int r = ch >> 3, c16 = ch & 7;   // row, 16B chunk
            uint32_t doff = r * 144 + c16 * 16;
            if (conv_mode) {
                int tap = t >> 2;
                int ci0 = (t & 3) * 64 + c16 * 8;
                int sl = l0 + r + tap - 1;
                uint32_t sz = ((unsigned)sl < (unsigned)L_) ? 16u : 0u;
                int slc = sl < 0 ? 0 : (sl >= L_ ? L_ - 1 : sl);
                cp16p(ab + doff, &A[((size_t)bidx * L_ + slc) * C_ + ci0], sz);
            } else {
                cp16p(ab + doff, &A[(m0 + r) * (size_t)K + t * 64 + c16 * 8], 16);
            }
            cp16p(bb + doff, &Bw[(n0 + r) * (size_t)K + t * 64 + c16 * 8], 16);
        }
    };
    (void)ldr_r; (void)ldr_c16;

    load_tile(0, 0); CP_COMMIT();
    load_tile(1, 1); CP_COMMIT();

    int slot = 0, nslot = 2;             // nslot = (t+2)%3 rotating
    for (int t = 0; t < ntls; t++) {
        if (t + 1 < ntls) CP_WAIT1(); else CP_WAIT0();
        __syncthreads();                  // slot(t) ready; slot(t-1) fully consumed
        if (t + 2 < ntls) { load_tile(t + 2, nslot); CP_COMMIT(); }

        uint32_t ab = sbase + (uint32_t)slot * TILEB;
        uint32_t bb = sbase + 3u * TILEB + (uint32_t)slot * TILEB;
        #pragma unroll
        for (int ks = 0; ks < 4; ks++) {
            int kb = ks * 16;
            uint32_t af[4][4], bf[4][2];
            #pragma unroll
            for (int mt = 0; mt < 4; mt++) {
                uint32_t a = ab + (uint32_t)(wm + mt*16 + (sel & 1)*8 + lr) * 144
                                + (uint32_t)(kb + (sel >> 1)*8) * 2;
                ldsm4(af[mt][0], af[mt][1], af[mt][2], af[mt][3], a);
            }
            #pragma unroll
            for (int q = 0; q < 2; q++) {
                uint32_t a = bb + (uint32_t)(wn + q*16 + (sel >> 1)*8 + lr) * 144
                                + (uint32_t)(kb + (sel & 1)*8) * 2;
                ldsm4(bf[q*2][0], bf[q*2][1], bf[q*2+1][0], bf[q*2+1][1], a);
            }
            #pragma unroll
            for (int mt = 0; mt < 4; mt++)
                #pragma unroll
                for (int nt = 0; nt < 4; nt++)
                    mma_f16(acc[mt][nt], af[mt][0], af[mt][1], af[mt][2], af[mt][3],
                            bf[nt][0], bf[nt][1]);
        }
        slot  = (slot  == 2) ? 0 : slot  + 1;
        nslot = (nslot == 2) ? 0 : nslot + 1;
    }

    // ---- epilogue ----------------------------------------------------------
    #pragma unroll
    for (int mt = 0; mt < 4; mt++)
        #pragma unroll
        for (int nt = 0; nt < 4; nt++)
            #pragma unroll
            for (int h = 0; h < 2; h++) {
                size_t row = m0 + wm + mt*16 + g + h*8;
                int col = (int)n0 + wn + nt*8 + tg*2;
                float v0 = acc[mt][nt][h*2+0], v1 = acc[mt][nt][h*2+1];
                if (epi == 1) { v0 = fmaxf(v0, 0.f); v1 = fmaxf(v1, 0.f); }
                else if (epi == 2) { v0 = 1.f/(1.f+expf(-v0)); v1 = 1.f/(1.f+expf(-v1)); }
                else if (epi >= 3) {
                    v0 = v0 * e1[col]   + e2[col];
                    v1 = v1 * e1[col+1] + e2[col+1];
                    if (epi == 4) { v0 = fmaxf(v0, 0.f); v1 = fmaxf(v1, 0.f); }
                }
                *(__half2*)&D[row * (size_t)N + col] = __floats2half2_rn(v0, v1);
            }
}

// ---------------- LayerNorm (fp16 data): warp per row, in-place ------------
__global__ void ln_kernel(__half* __restrict__ data,
                          const float* __restrict__ gw, const float* __restrict__ bw) {
    int lane = threadIdx.x & 31, warp = threadIdx.x >> 5;
    size_t row = (size_t)blockIdx.x * 8 + warp;
    uint4* p = (uint4*)(data + row * C_);
    uint4 raw = p[lane];
    __half2 hp[4];
    *(uint4*)hp = raw;
    float v[8];
    #pragma unroll
    for (int q = 0; q < 4; q++) {
        float2 f = __half22float2(hp[q]);
        v[q*2] = f.x; v[q*2+1] = f.y;
    }
    float s = 0.f;
    #pragma unroll
    for (int j = 0; j < 8; j++) s += v[j];
    #pragma unroll
    for (int o = 16; o; o >>= 1) s += __shfl_xor_sync(0xffffffffu, s, o);
    float mean = s * (1.f / C_);
    float s2 = 0.f;
    #pragma unroll
    for (int j = 0; j < 8; j++) { v[j] -= mean; s2 += v[j]*v[j]; }
    #pragma unroll
    for (int o = 16; o; o >>= 1) s2 += __shfl_xor_sync(0xffffffffu, s2, o);
    float inv = rsqrtf(s2 * (1.f / C_) + 1e-6f);

    const float4* g4 = (const float4*)gw;
    const float4* b4 = (const float4*)bw;
    float4 ga = g4[lane*2], gb = g4[lane*2+1], ba = b4[lane*2], bb = b4[lane*2+1];
    float gv[8] = {ga.x, ga.y, ga.z, ga.w, gb.x, gb.y, gb.z, gb.w};
    float bv[8] = {ba.x, ba.y, ba.z, ba.w, bb.x, bb.y, bb.z, bb.w};
    #pragma unroll
    for (int q = 0; q < 4; q++)
        hp[q] = __floats2half2_rn(v[q*2]*inv*gv[q*2] + bv[q*2],
                                  v[q*2+1]*inv*gv[q*2+1] + bv[q*2+1]);
    p[lane] = *(uint4*)hp;
}

// ==== fused LN2 + final: out[b,c,l] = relu(xp[b,l,c]*LN(fw)[b,l,c] + x) ====
// grid (L_/32, B_), block 256 = 8 warps; warp handles 4 rows (stride 8).
__global__ void ln_final_kernel(const __half* __restrict__ t1, const __half* __restrict__ xp,
                                const float* __restrict__ x,
                                const float* __restrict__ gw, const float* __restrict__ bw,
                                float* __restrict__ out) {
    __shared__ float tile[32][257];
    int tid = threadIdx.x, lane = tid & 31, warp = tid >> 5;
    int b = blockIdx.y, l0 = blockIdx.x * 32;

    const float4* g4 = (const float4*)gw;
    const float4* b4 = (const float4*)bw;
    float4 ga = g4[lane*2], gb = g4[lane*2+1], ba = b4[lane*2], bb = b4[lane*2+1];
    float gv[8] = {ga.x, ga.y, ga.z, ga.w, gb.x, gb.y, gb.z, gb.w};
    float bv[8] = {ba.x, ba.y, ba.z, ba.w, bb.x, bb.y, bb.z, bb.w};

    #pragma unroll
    for (int r = 0; r < 4; r++) {
        int rt = r * 8 + warp;                       // row in tile
        size_t row = (size_t)b * L_ + l0 + rt;
        uint4 raw = ((const uint4*)(t1 + row * C_))[lane];
        __half2 hp[4]; *(uint4*)hp = raw;
        float v[8];
        #pragma unroll
        for (int q = 0; q < 4; q++) {
            float2 f = __half22float2(hp[q]);
            v[q*2] = f.x; v[q*2+1] = f.y;
        }
        float s = 0.f;
        #pragma unroll
        for (int j = 0; j < 8; j++) s += v[j];
        #pragma unroll
        for (int o = 16; o; o >>= 1) s += __shfl_xor_sync(0xffffffffu, s, o);
        float mean = s * (1.f / C_);
        float s2 = 0.f;
        #pragma unroll
        for (int j = 0; j < 8; j++) { v[j] -= mean; s2 += v[j]*v[j]; }
        #pragma unroll
        for (int o = 16; o; o >>= 1) s2 += __shfl_xor_sync(0xffffffffu, s2, o);
        float inv = rsqrtf(s2 * (1.f / C_) + 1e-6f);

        uint4 xraw = ((const uint4*)(xp + row * C_))[lane];
        __half2 xh[4]; *(uint4*)xh = xraw;
        #pragma unroll
        for (int q = 0; q < 4; q++) {
            float2 xf = __half22float2(xh[q]);
            float fw0 = v[q*2]   * inv * gv[q*2]   + bv[q*2];
            float fw1 = v[q*2+1] * inv * gv[q*2+1] + bv[q*2+1];
            tile[rt][lane*8 + q*2]     = xf.x * fw0;
            tile[rt][lane*8 + q*2 + 1] = xf.y * fw1;
        }
    }
    __syncthreads();

    int lidx = tid & 31;     // l within tile
    int cg = tid >> 5;       // 0..7 -> 32 c each
    #pragma unroll
    for (int j = 0; j < 32; j++) {
        int c = cg * 32 + j;
        size_t gi = ((size_t)b * C_ + c) * L_ + l0 + lidx;
        out[gi] = fmaxf(tile[lidx][c] + x[gi], 0.f);
    }
}

// ---------------------------------------------------------------------------
extern "C" void kernel_launch(void* const* d_in, const int* in_sizes, int n_in,
                              void* d_out, int out_size) {
    const float* x       = (const float*)d_in[0];
    const float* conv1_w = (const float*)d_in[1];
    const float* bn1_g   = (const float*)d_in[2];
    const float* bn1_b   = (const float*)d_in[3];
    const float* bn1_m   = (const float*)d_in[4];
    const float* bn1_v   = (const float*)d_in[5];
    const float* conv2_w = (const float*)d_in[6];
    const float* bn2_g   = (const float*)d_in[7];
    const float* bn2_b   = (const float*)d_in[8];
    const float* bn2_m   = (const float*)d_in[9];
    const float* bn2_v   = (const float*)d_in[10];
    const float* fc1_w   = (const float*)d_in[11];
    const float* fc2_w   = (const float*)d_in[12];
    const float* ln_g    = (const float*)d_in[13];
    const float* ln_b    = (const float*)d_in[14];
    float* out = (float*)d_out;

    void *xt, *y1, *xp, *t1, *h, *dct, *fc1r, *fc2r, *w1r, *w2r;
    void *bn1s, *bn1t, *bn2s, *bn2t;
    cudaGetSymbolAddress(&xt,   g_xt);
    cudaGetSymbolAddress(&y1,   g_y1);
    cudaGetSymbolAddress(&xp,   g_xp);
    cudaGetSymbolAddress(&t1,   g_t1);
    cudaGetSymbolAddress(&h,    g_h);
    cudaGetSymbolAddress(&dct,  g_dct);
    cudaGetSymbolAddress(&fc1r, g_fc1r);
    cudaGetSymbolAddress(&fc2r, g_fc2r);
    cudaGetSymbolAddress(&w1r,  g_w1r);
    cudaGetSymbolAddress(&w2r,  g_w2r);
    cudaGetSymbolAddress(&bn1s, g_bn1s);
    cudaGetSymbolAddress(&bn1t, g_bn1t);
    cudaGetSymbolAddress(&bn2s, g_bn2s);
    cudaGetSymbolAddress(&bn2t, g_bn2t);

    cudaFuncSetAttribute(gemmh, cudaFuncAttributeMaxDynamicSharedMemorySize, GH_SMEM);

    // 0. precompute fp16 weights + transpose/round x
    precompute_kernel<<<(3*C_*C_ + 255)/256, 256>>>(
        fc1_w, fc2_w, conv1_w, conv2_w,
        bn1_g, bn1_b, bn1_m, bn1_v, bn2_g, bn2_b, bn2_m, bn2_v);
    {
        dim3 grid(C_/32, L_/32, B_);
        transpose_round_kernel<<<grid, dim3(32, 8)>>>(x, (__half*)xt);
    }

    // 1. conv1+bn1+relu -> y1 [B,L,C]
    gemmh<<<dim3(C_/128, BL_/128), 256, GH_SMEM>>>(
        (const __half*)xt, (const __half*)w1r, (__half*)y1, C_, 3*C_, 1,
        (const float*)bn1s, (const float*)bn1t, 4);
    // 2. conv2+bn2 -> xp [B,L,C]
    gemmh<<<dim3(C_/128, BL_/128), 256, GH_SMEM>>>(
        (const __half*)y1, (const __half*)w2r, (__half*)xp, C_, 3*C_, 1,
        (const float*)bn2s, (const float*)bn2t, 3);
    // 3. freq = xp @ Dm^T -> t1
    gemmh<<<dim3(C_/128, BL_/128), 256, GH_SMEM>>>(
        (const __half*)xp, (const __half*)dct, (__half*)t1, C_, C_, 0,
        nullptr, nullptr, 0);
    // 4. sd = LN(freq)
    ln_kernel<<<BL_/8, 256>>>((__half*)t1, ln_g, ln_b);
    // 5. h = relu(sd @ fc1^T)
    gemmh<<<dim3(H_/128, BL_/128), 256, GH_SMEM>>>(
        (const __half*)t1, (const __half*)fc1r, (__half*)h, H_, C_, 0,
        nullptr, nullptr, 1);
    // 6. fw = sigmoid(h @ fc2^T) -> t1
    gemmh<<<dim3(C_/128, BL_/128), 256, GH_SMEM>>>(
        (const __half*)h, (const __half*)fc2r, (__half*)t1, C_, H_, 0,
        nullptr, nullptr, 2);
    // 7+8. fused: fw = LN(t1); out = relu(transpose(xp*fw) + x)
    {
        dim3 grid(L_/32, B_);
        ln_final_kernel<<<grid, 256>>>((const __half*)t1, (const __half*)xp, x,
                                       ln_g, ln_b, out);
    }
}